// round 5
// baseline (speedup 1.0000x reference)
#include <cuda_runtime.h>
#include <cuda_bf16.h>
#include <math.h>
#include <stdint.h>

// Problem constants
#define NSTEPS_MAX 32768
#define ISZ 1024
#define H   512
#define MB  100
#define D   1536

// Px layout (per-step precomputed x-projections + biases), padded stride
#define STRIDE 1280
#define OFF_C  0      // 512: x@Wc_x + bc
#define OFF_WG 512    // 1  : x@Wwg_x + bwg
#define OFF_WP 516    // 100: x@Wwp_x + bwp
#define OFF_RG 616    // 1
#define OFF_RP 620    // 100
#define OFF_H  720    // 512: x@Wxh + bh

#define NC 16         // CTAs in recurrence kernel

// ---------------- device global scratch (no runtime alloc allowed) ----------------
__device__ float g_Px[(size_t)NSTEPS_MAX * STRIDE];   // ~168 MB
__device__ float g_Wcat[(size_t)ISZ * STRIDE];        // 5.2 MB
__device__ float g_bcat[STRIDE];

__device__ float g_pc[NC * H];      // phase-1 partials of h@Wc_h
__device__ float g_rpp[NC * MB];    // partials of h@Wrp_h
__device__ float g_wpp[NC * MB];    // partials of h@Wwp_h
__device__ float g_rgp[NC];
__device__ float g_wgp[NC];
__device__ float g_pout[NC * H];    // partials of h@Whh + r@Wrh

__device__ unsigned g_count;                 // zero-init; returns to 0 each barrier
__device__ volatile unsigned g_epoch;        // monotonically increasing, equality-compared

// ---------------- global barrier (16 co-resident CTAs) ----------------
__device__ __forceinline__ void gbarrier() {
    __syncthreads();
    if (threadIdx.x == 0) {
        __threadfence();                       // publish my prior global stores
        unsigned e = g_epoch;
        if (atomicAdd(&g_count, 1u) == NC - 1u) {
            g_count = 0u;
            __threadfence();
            g_epoch = e + 1u;                  // release
        } else {
            while (g_epoch == e) { }           // spin on L2 (volatile)
            __threadfence();                   // acquire
        }
    }
    __syncthreads();
}

// ---------------- kernel 1: build concatenated weight/bias ----------------
__global__ void prep_kernel(const float* __restrict__ Wc,  const float* __restrict__ bc,
                            const float* __restrict__ Wwg, const float* __restrict__ bwg,
                            const float* __restrict__ Wwp, const float* __restrict__ bwp,
                            const float* __restrict__ Wrg, const float* __restrict__ brg,
                            const float* __restrict__ Wrp, const float* __restrict__ brp,
                            const float* __restrict__ Wxh, const float* __restrict__ bh) {
    int idx = blockIdx.x * blockDim.x + threadIdx.x;
    if (idx < ISZ * STRIDE) {
        int k = idx / STRIDE, n = idx % STRIDE;
        float v = 0.f;
        if (n < 512)                          v = Wc[(size_t)k * H + n];
        else if (n == OFF_WG)                 v = Wwg[k];
        else if (n >= OFF_WP && n < OFF_WP + MB) v = Wwp[(size_t)k * MB + (n - OFF_WP)];
        else if (n == OFF_RG)                 v = Wrg[k];
        else if (n >= OFF_RP && n < OFF_RP + MB) v = Wrp[(size_t)k * MB + (n - OFF_RP)];
        else if (n >= OFF_H && n < OFF_H + H) v = Wxh[(size_t)k * H + (n - OFF_H)];
        g_Wcat[idx] = v;
    }
    if (idx < STRIDE) {
        int n = idx;
        float b = 0.f;
        if (n < 512)                          b = bc[n];
        else if (n == OFF_WG)                 b = bwg[0];
        else if (n >= OFF_WP && n < OFF_WP + MB) b = bwp[n - OFF_WP];
        else if (n == OFF_RG)                 b = brg[0];
        else if (n >= OFF_RP && n < OFF_RP + MB) b = brp[n - OFF_RP];
        else if (n >= OFF_H && n < OFF_H + H) b = bh[n - OFF_H];
        g_bcat[n] = b;
    }
}

// ---------------- kernel 2: Px = X @ Wcat + bcat (tiled fp32 GEMM) ----------------
// BM=128, BN=64, BK=16, 256 threads, 8x4 per-thread tile.
__global__ void __launch_bounds__(256) gemm_kernel(const float* __restrict__ X) {
    __shared__ float As[16][128];      // transposed A tile
    __shared__ float Bs[16][64];

    const int tid = threadIdx.x;
    const int bm = blockIdx.x * 128;
    const int bn = blockIdx.y * 64;

    const int ty = tid >> 4;           // 0..15  -> m group (8 rows)
    const int tx = tid & 15;           // 0..15  -> n group (4 cols)

    float acc[8][4];
#pragma unroll
    for (int i = 0; i < 8; i++)
#pragma unroll
        for (int j = 0; j < 4; j++) acc[i][j] = 0.f;

    const int a_m = tid >> 2;          // 0..63
    const int a_k = (tid & 3) * 4;     // 0,4,8,12
    const int b_k = tid >> 4;          // 0..15
    const int b_n = (tid & 15) * 4;

    for (int k0 = 0; k0 < ISZ; k0 += 16) {
        float4 v0 = *reinterpret_cast<const float4*>(&X[(size_t)(bm + a_m) * ISZ + k0 + a_k]);
        float4 v1 = *reinterpret_cast<const float4*>(&X[(size_t)(bm + a_m + 64) * ISZ + k0 + a_k]);
        float4 w  = *reinterpret_cast<const float4*>(&g_Wcat[(size_t)(k0 + b_k) * STRIDE + bn + b_n]);
        As[a_k + 0][a_m] = v0.x; As[a_k + 1][a_m] = v0.y;
        As[a_k + 2][a_m] = v0.z; As[a_k + 3][a_m] = v0.w;
        As[a_k + 0][a_m + 64] = v1.x; As[a_k + 1][a_m + 64] = v1.y;
        As[a_k + 2][a_m + 64] = v1.z; As[a_k + 3][a_m + 64] = v1.w;
        *reinterpret_cast<float4*>(&Bs[b_k][b_n]) = w;
        __syncthreads();
#pragma unroll
        for (int kk = 0; kk < 16; kk++) {
            float a[8], b[4];
#pragma unroll
            for (int i = 0; i < 8; i++) a[i] = As[kk][ty * 8 + i];
#pragma unroll
            for (int j = 0; j < 4; j++) b[j] = Bs[kk][tx * 4 + j];
#pragma unroll
            for (int i = 0; i < 8; i++)
#pragma unroll
                for (int j = 0; j < 4; j++) acc[i][j] = fmaf(a[i], b[j], acc[i][j]);
        }
        __syncthreads();
    }
#pragma unroll
    for (int i = 0; i < 8; i++) {
        int row = bm + ty * 8 + i;
        int col = bn + tx * 4;
        float4 o;
        o.x = acc[i][0] + g_bcat[col + 0];
        o.y = acc[i][1] + g_bcat[col + 1];
        o.z = acc[i][2] + g_bcat[col + 2];
        o.w = acc[i][3] + g_bcat[col + 3];
        *reinterpret_cast<float4*>(&g_Px[(size_t)row * STRIDE + col]) = o;
    }
}

// ---------------- kernel 3: sequential recurrence (16 CTAs x 512 threads) ----------------
__global__ void __launch_bounds__(512, 1) recur_kernel(
    const float* __restrict__ Wc,  const float* __restrict__ Wrg,
    const float* __restrict__ Wrp, const float* __restrict__ Wwg,
    const float* __restrict__ Wwp, const float* __restrict__ Wrh,
    const float* __restrict__ Whh, float* __restrict__ out,
    const int* __restrict__ nImgP) {

    __shared__ float s_h[H];
    __shared__ float s_wrp[MB][33];
    __shared__ float s_wwp[MB][33];
    __shared__ float s_wrg[32];
    __shared__ float s_wwg[32];
    __shared__ float s_mem[MB][33];
    __shared__ float s_ar[MB];
    __shared__ float s_aw[MB];
    __shared__ float s_c[32];
    __shared__ float s_r[32];
    __shared__ float s_g[4];   // [0]=rg logit [1]=wg logit [2]=go [3]=gw

    const int t = threadIdx.x;
    const int j = blockIdx.x;
    const int base = j * 32;   // this CTA's 32 h-rows / r-rows / mem-cols

    // register-resident weight columns: thread t owns output column t
    float wc[32], whh[32], wrh[32];
#pragma unroll
    for (int i = 0; i < 32; i++) {
        wc[i]  = Wc[(size_t)(ISZ + base + i) * H + t];
        whh[i] = Whh[(size_t)(base + i) * H + t];
        wrh[i] = Wrh[(size_t)(base + i) * H + t];
    }
    // SMEM weights (transposed, padded)
    for (int idx = t; idx < MB * 32; idx += 512) {
        int k = idx >> 5, i = idx & 31;
        s_wrp[k][i] = Wrp[(size_t)(ISZ + base + i) * MB + k];
        s_wwp[k][i] = Wwp[(size_t)(ISZ + base + i) * MB + k];
    }
    if (t < 32) { s_wrg[t] = Wrg[ISZ + base + t]; s_wwg[t] = Wwg[ISZ + base + t]; }
    for (int idx = t; idx < MB * 33; idx += 512) ((float*)s_mem)[idx] = 0.f;
    s_h[t] = 0.f;
    __syncthreads();

    int nSteps = *nImgP;
    if (nSteps > NSTEPS_MAX) nSteps = NSTEPS_MAX;

    for (int s = 0; s < nSteps; s++) {
        const float* px = g_Px + (size_t)s * STRIDE;

        // ===== phase 1: h-slice projections -> global partials =====
        {
            float acc = 0.f;
#pragma unroll
            for (int i = 0; i < 32; i++) acc = fmaf(s_h[base + i], wc[i], acc);
            g_pc[j * H + t] = acc;
        }
        if (t < MB) {
            float a = 0.f;
#pragma unroll
            for (int i = 0; i < 32; i++) a = fmaf(s_wrp[t][i], s_h[base + i], a);
            g_rpp[j * MB + t] = a;
        } else if (t < 2 * MB) {
            const int k = t - MB;
            float a = 0.f;
#pragma unroll
            for (int i = 0; i < 32; i++) a = fmaf(s_wwp[k][i], s_h[base + i], a);
            g_wpp[j * MB + k] = a;
        } else if (t == 2 * MB) {
            float a = 0.f;
#pragma unroll
            for (int i = 0; i < 32; i++) a = fmaf(s_wrg[i], s_h[base + i], a);
            g_rgp[j] = a;
        } else if (t == 2 * MB + 1) {
            float a = 0.f;
#pragma unroll
            for (int i = 0; i < 32; i++) a = fmaf(s_wwg[i], s_h[base + i], a);
            g_wgp[j] = a;
        }
        gbarrier();   // includes threadfence

        // ===== phase 2: reduce partials, gates/softmax, r, mem update, out-partials =====
        if (t < MB) {
            float a = px[OFF_RP + t];
#pragma unroll
            for (int j2 = 0; j2 < NC; j2++) a += __ldcg(&g_rpp[j2 * MB + t]);
            s_ar[t] = a;
        } else if (t < 2 * MB) {
            const int k = t - MB;
            float a = px[OFF_WP + k];
#pragma unroll
            for (int j2 = 0; j2 < NC; j2++) a += __ldcg(&g_wpp[j2 * MB + k]);
            s_aw[k] = a;
        } else if (t == 200) {
            float a = px[OFF_RG];
#pragma unroll
            for (int j2 = 0; j2 < NC; j2++) a += __ldcg(&g_rgp[j2]);
            s_g[0] = a;
        } else if (t == 201) {
            float a = px[OFF_WG];
#pragma unroll
            for (int j2 = 0; j2 < NC; j2++) a += __ldcg(&g_wgp[j2]);
            s_g[1] = a;
        } else if (t >= 256 && t < 288) {
            const int cl = t - 256;
            float a = px[OFF_C + base + cl];
#pragma unroll
            for (int j2 = 0; j2 < NC; j2++) a += __ldcg(&g_pc[j2 * H + base + cl]);
            s_c[cl] = fmaxf(a, 0.f);      // c = relu(xh@Wc + bc), local cols only
        }
        __syncthreads();

        // softmax: warp0 -> ar, warp1 -> aw; gates on warp2
        if (t < 32) {
            float m = -INFINITY;
            for (int k = t; k < MB; k += 32) m = fmaxf(m, s_ar[k]);
#pragma unroll
            for (int o = 16; o; o >>= 1) m = fmaxf(m, __shfl_xor_sync(0xFFFFFFFFu, m, o));
            float ssum = 0.f;
            for (int k = t; k < MB; k += 32) { float e = __expf(s_ar[k] - m); s_ar[k] = e; ssum += e; }
#pragma unroll
            for (int o = 16; o; o >>= 1) ssum += __shfl_xor_sync(0xFFFFFFFFu, ssum, o);
            float inv = 1.f / ssum;
            for (int k = t; k < MB; k += 32) s_ar[k] *= inv;
        } else if (t < 64) {
            const int l = t - 32;
            float m = -INFINITY;
            for (int k = l; k < MB; k += 32) m = fmaxf(m, s_aw[k]);
#pragma unroll
            for (int o = 16; o; o >>= 1) m = fmaxf(m, __shfl_xor_sync(0xFFFFFFFFu, m, o));
            float ssum = 0.f;
            for (int k = l; k < MB; k += 32) { float e = __expf(s_aw[k] - m); s_aw[k] = e; ssum += e; }
#pragma unroll
            for (int o = 16; o; o >>= 1) ssum += __shfl_xor_sync(0xFFFFFFFFu, ssum, o);
            float inv = 1.f / ssum;
            for (int k = l; k < MB; k += 32) s_aw[k] *= inv;
        } else if (t == 64) {
            s_g[2] = 1.f / (1.f + __expf(-s_g[0]));   // go
        } else if (t == 65) {
            s_g[3] = 1.f / (1.f + __expf(-s_g[1]));   // gw
        }
        __syncthreads();

        // r slice: r[base+cl] = go * sum_m ar[m]*mem[m][cl]
        if (t < 32) {
            float a = 0.f;
            for (int m2 = 0; m2 < MB; m2++) a = fmaf(s_ar[m2], s_mem[m2][t], a);
            s_r[t] = s_g[2] * a;
        }
        __syncthreads();

        // out-partial: h_slice@Whh + r_slice@Wrh (512-wide)
        {
            float acc = 0.f;
#pragma unroll
            for (int i = 0; i < 32; i++) acc = fmaf(s_h[base + i], whh[i], acc);
#pragma unroll
            for (int i = 0; i < 32; i++) acc = fmaf(s_r[i], wrh[i], acc);
            g_pout[j * H + t] = acc;
        }
        // memory write (uses OLD mem, already consumed by r above this barrier)
        {
            const float gw = s_g[3];
            for (int idx = t; idx < MB * 32; idx += 512) {
                const int m2 = idx >> 5, cl = idx & 31;
                const float aw = s_aw[m2];
                s_mem[m2][cl] = gw * aw * s_c[cl] + (1.f - aw) * s_mem[m2][cl];
            }
        }
        gbarrier();

        // ===== phase 3: full reduction -> h_new (redundant in every CTA) =====
        {
            float pre = px[OFF_H + t];
#pragma unroll
            for (int j2 = 0; j2 < NC; j2++) pre += __ldcg(&g_pout[j2 * H + t]);
            float hn = fmaxf(pre, 0.f);
            if ((t >> 5) == j) out[(size_t)s * H + t] = hn;
            s_h[t] = hn;
        }
        __syncthreads();
    }
}

// ---------------- launcher ----------------
extern "C" void kernel_launch(void* const* d_in, const int* in_sizes, int n_in,
                              void* d_out, int out_size) {
    const float* X    = (const float*)d_in[0];
    const float* Wc   = (const float*)d_in[1];
    const float* bc   = (const float*)d_in[2];
    const float* Wwg  = (const float*)d_in[3];
    const float* bwg  = (const float*)d_in[4];
    const float* Wwp  = (const float*)d_in[5];
    const float* bwp  = (const float*)d_in[6];
    const float* Wrg  = (const float*)d_in[7];
    const float* brg  = (const float*)d_in[8];
    const float* Wrp  = (const float*)d_in[9];
    const float* brp  = (const float*)d_in[10];
    const float* Wxh  = (const float*)d_in[11];
    const float* Wrh  = (const float*)d_in[12];
    const float* Whh  = (const float*)d_in[13];
    const float* bh   = (const float*)d_in[14];
    const int*   nImg = (const int*)d_in[15];

    prep_kernel<<<(ISZ * STRIDE + 255) / 256, 256>>>(Wc, bc, Wwg, bwg, Wwp, bwp,
                                                     Wrg, brg, Wrp, brp, Wxh, bh);
    dim3 ggrid(NSTEPS_MAX / 128, STRIDE / 64);
    gemm_kernel<<<ggrid, 256>>>(X);
    recur_kernel<<<NC, 512>>>(Wc, Wrg, Wrp, Wwg, Wwp, Wrh, Whh, (float*)d_out, nImg);
}

// round 7
// speedup vs baseline: 1.1537x; 1.1537x over previous
#include <cuda_runtime.h>
#include <cuda_bf16.h>
#include <math.h>
#include <stdint.h>

// Problem constants
#define NSTEPS_MAX 32768
#define ISZ 1024
#define H   512
#define MB  100

// Px layout (per-step precomputed x-projections + biases), padded stride
#define STRIDE 1280
#define OFF_C  0      // 512: x@Wc_x + bc
#define OFF_WG 512    // 1  : x@Wwg_x + bwg
#define OFF_WP 516    // 100: x@Wwp_x + bwp
#define OFF_RG 616    // 1
#define OFF_RP 620    // 100
#define OFF_H  720    // 512: x@Wxh + bh

#define NC 16         // CTAs in recurrence kernel

// ---------------- device global scratch (no runtime alloc allowed) ----------------
__device__ float g_Px[(size_t)NSTEPS_MAX * STRIDE];   // ~168 MB
__device__ float g_Wcat[(size_t)ISZ * STRIDE];        // 5.2 MB
__device__ float g_bcat[STRIDE];

// partials, transposed layout [elem][16] so consumers read 4 x float4
__device__ __align__(16) float g_pc[H * NC];
__device__ __align__(16) float g_rpp[MB * NC];
__device__ __align__(16) float g_wpp[MB * NC];
__device__ __align__(16) float g_rgp[NC];
__device__ __align__(16) float g_wgp[NC];
__device__ __align__(16) float g_pout[H * NC];

__device__ unsigned g_flagA[NC];   // monotonic step tags (zero-init at load)
__device__ unsigned g_flagB[NC];

// ---------------- kernel 1: build concatenated weight/bias ----------------
__global__ void prep_kernel(const float* __restrict__ Wc,  const float* __restrict__ bc,
                            const float* __restrict__ Wwg, const float* __restrict__ bwg,
                            const float* __restrict__ Wwp, const float* __restrict__ bwp,
                            const float* __restrict__ Wrg, const float* __restrict__ brg,
                            const float* __restrict__ Wrp, const float* __restrict__ brp,
                            const float* __restrict__ Wxh, const float* __restrict__ bh) {
    int idx = blockIdx.x * blockDim.x + threadIdx.x;
    if (idx < ISZ * STRIDE) {
        int k = idx / STRIDE, n = idx % STRIDE;
        float v = 0.f;
        if (n < 512)                          v = Wc[(size_t)k * H + n];
        else if (n == OFF_WG)                 v = Wwg[k];
        else if (n >= OFF_WP && n < OFF_WP + MB) v = Wwp[(size_t)k * MB + (n - OFF_WP)];
        else if (n == OFF_RG)                 v = Wrg[k];
        else if (n >= OFF_RP && n < OFF_RP + MB) v = Wrp[(size_t)k * MB + (n - OFF_RP)];
        else if (n >= OFF_H && n < OFF_H + H) v = Wxh[(size_t)k * H + (n - OFF_H)];
        g_Wcat[idx] = v;
    }
    if (idx < STRIDE) {
        int n = idx;
        float b = 0.f;
        if (n < 512)                          b = bc[n];
        else if (n == OFF_WG)                 b = bwg[0];
        else if (n >= OFF_WP && n < OFF_WP + MB) b = bwp[n - OFF_WP];
        else if (n == OFF_RG)                 b = brg[0];
        else if (n >= OFF_RP && n < OFF_RP + MB) b = brp[n - OFF_RP];
        else if (n >= OFF_H && n < OFF_H + H) b = bh[n - OFF_H];
        g_bcat[n] = b;
    }
}

// ---------------- kernel 2: Px = X @ Wcat + bcat (tiled fp32 GEMM) ----------------
__global__ void __launch_bounds__(256) gemm_kernel(const float* __restrict__ X) {
    __shared__ float As[16][128];
    __shared__ float Bs[16][64];

    const int tid = threadIdx.x;
    const int bm = blockIdx.x * 128;
    const int bn = blockIdx.y * 64;

    const int ty = tid >> 4;
    const int tx = tid & 15;

    float acc[8][4];
#pragma unroll
    for (int i = 0; i < 8; i++)
#pragma unroll
        for (int j = 0; j < 4; j++) acc[i][j] = 0.f;

    const int a_m = tid >> 2;
    const int a_k = (tid & 3) * 4;
    const int b_k = tid >> 4;
    const int b_n = (tid & 15) * 4;

    for (int k0 = 0; k0 < ISZ; k0 += 16) {
        float4 v0 = *reinterpret_cast<const float4*>(&X[(size_t)(bm + a_m) * ISZ + k0 + a_k]);
        float4 v1 = *reinterpret_cast<const float4*>(&X[(size_t)(bm + a_m + 64) * ISZ + k0 + a_k]);
        float4 w  = *reinterpret_cast<const float4*>(&g_Wcat[(size_t)(k0 + b_k) * STRIDE + bn + b_n]);
        As[a_k + 0][a_m] = v0.x; As[a_k + 1][a_m] = v0.y;
        As[a_k + 2][a_m] = v0.z; As[a_k + 3][a_m] = v0.w;
        As[a_k + 0][a_m + 64] = v1.x; As[a_k + 1][a_m + 64] = v1.y;
        As[a_k + 2][a_m + 64] = v1.z; As[a_k + 3][a_m + 64] = v1.w;
        *reinterpret_cast<float4*>(&Bs[b_k][b_n]) = w;
        __syncthreads();
#pragma unroll
        for (int kk = 0; kk < 16; kk++) {
            float a[8], b[4];
#pragma unroll
            for (int i = 0; i < 8; i++) a[i] = As[kk][ty * 8 + i];
#pragma unroll
            for (int j = 0; j < 4; j++) b[j] = Bs[kk][tx * 4 + j];
#pragma unroll
            for (int i = 0; i < 8; i++)
#pragma unroll
                for (int j = 0; j < 4; j++) acc[i][j] = fmaf(a[i], b[j], acc[i][j]);
        }
        __syncthreads();
    }
#pragma unroll
    for (int i = 0; i < 8; i++) {
        int row = bm + ty * 8 + i;
        int col = bn + tx * 4;
        float4 o;
        o.x = acc[i][0] + g_bcat[col + 0];
        o.y = acc[i][1] + g_bcat[col + 1];
        o.z = acc[i][2] + g_bcat[col + 2];
        o.w = acc[i][3] + g_bcat[col + 3];
        *reinterpret_cast<float4*>(&g_Px[(size_t)row * STRIDE + col]) = o;
    }
}

// ---------------- helpers ----------------
__device__ __forceinline__ float red16_cg(const float* p) {
    float4 a = __ldcg((const float4*)(p + 0));
    float4 b = __ldcg((const float4*)(p + 4));
    float4 c = __ldcg((const float4*)(p + 8));
    float4 d = __ldcg((const float4*)(p + 12));
    return ((a.x + a.y) + (a.z + a.w)) + ((b.x + b.y) + (b.z + b.w))
         + ((c.x + c.y) + (c.z + c.w)) + ((d.x + d.y) + (d.z + d.w));
}

// SMEM px tile layout (272 floats):
//   [0..32)    : C slice (cols base..base+32)
//   [32..240)  : mid block g_Px[512..720): WG@32, WP@36+k, RG@136, RP@140+k
//   [240..272) : H slice (cols base..base+32)
#define PX_WG 32
#define PX_WP 36
#define PX_RG 136
#define PX_RP 140
#define PX_H  240

// ---------------- kernel 3: sequential recurrence (16 CTAs x 512 threads) ----------------
__global__ void __launch_bounds__(512, 1) recur_kernel(
    const float* __restrict__ Wc,  const float* __restrict__ Wrg,
    const float* __restrict__ Wrp, const float* __restrict__ Wwg,
    const float* __restrict__ Wwp, const float* __restrict__ Wrh,
    const float* __restrict__ Whh, float* __restrict__ out,
    const int* __restrict__ nImgP) {

    __shared__ float s_hl[32];              // this CTA's h slice
    __shared__ float s_wrp[MB][33];
    __shared__ float s_wwp[MB][33];
    __shared__ float s_wrg[32];
    __shared__ float s_wwg[32];
    __shared__ float s_mem[MB][33];
    __shared__ float s_ar[MB];              // holds unnormalized exp(e)
    __shared__ float s_aw[MB];              // holds unnormalized exp(e)
    __shared__ float s_c[32];
    __shared__ float s_r[32];
    __shared__ float s_rp[4][33];
    __shared__ float s_g[8];   // 0=rg logit 1=wg logit 2=go/sum_r 3=gw 4=inv_sum_w
    __shared__ __align__(16) float s_px[2][272];
    __shared__ unsigned s_base;

    const int t = threadIdx.x;
    const int j = blockIdx.x;
    const int base = j * 32;

    // register-resident weight columns: thread t owns output column t
    float wc[32], whh[32], wrh[32];
#pragma unroll
    for (int i = 0; i < 32; i++) {
        wc[i]  = Wc[(size_t)(ISZ + base + i) * H + t];
        whh[i] = Whh[(size_t)(base + i) * H + t];
        wrh[i] = Wrh[(size_t)(base + i) * H + t];
    }
    for (int idx = t; idx < MB * 32; idx += 512) {
        int k = idx >> 5, i = idx & 31;
        s_wrp[k][i] = Wrp[(size_t)(ISZ + base + i) * MB + k];
        s_wwp[k][i] = Wwp[(size_t)(ISZ + base + i) * MB + k];
    }
    if (t < 32) { s_wrg[t] = Wrg[ISZ + base + t]; s_wwg[t] = Wwg[ISZ + base + t]; }
    for (int idx = t; idx < MB * 33; idx += 512) ((float*)s_mem)[idx] = 0.f;
    if (t < 32) s_hl[t] = 0.f;
    if (t == 0) s_base = *(volatile unsigned*)&g_flagA[j];   // replay-safe tag base
    __syncthreads();

    int nSteps = *nImgP;
    if (nSteps > NSTEPS_MAX) nSteps = NSTEPS_MAX;
    if (nSteps <= 0) return;
    const unsigned tag0 = s_base;

    // --- prologue prefetch: step 0 into buffer 0 ---
    {
        const float* row = g_Px;  // step 0
        if (t < 68) {
            const float* src; float* dst;
            if (t < 8)       { src = row + OFF_C + base + t * 4;        dst = &s_px[0][t * 4]; }
            else if (t < 60) { src = row + 512 + (t - 8) * 4;           dst = &s_px[0][32 + (t - 8) * 4]; }
            else             { src = row + OFF_H + base + (t - 60) * 4; dst = &s_px[0][240 + (t - 60) * 4]; }
            unsigned ds = (unsigned)__cvta_generic_to_shared(dst);
            asm volatile("cp.async.cg.shared.global [%0], [%1], 16;" :: "r"(ds), "l"(src));
        }
        asm volatile("cp.async.commit_group;" ::: "memory");
    }

    for (int s = 0; s < nSteps; s++) {
        const int cur = s & 1;
        const unsigned tag = tag0 + (unsigned)s + 1u;

        // --- prefetch step s+1 into other buffer ---
        {
            int sp = s + 1; if (sp >= nSteps) sp = nSteps - 1;
            const float* row = g_Px + (size_t)sp * STRIDE;
            if (t < 68) {
                const float* src; float* dst;
                if (t < 8)       { src = row + OFF_C + base + t * 4;        dst = &s_px[cur ^ 1][t * 4]; }
                else if (t < 60) { src = row + 512 + (t - 8) * 4;           dst = &s_px[cur ^ 1][32 + (t - 8) * 4]; }
                else             { src = row + OFF_H + base + (t - 60) * 4; dst = &s_px[cur ^ 1][240 + (t - 60) * 4]; }
                unsigned ds = (unsigned)__cvta_generic_to_shared(dst);
                asm volatile("cp.async.cg.shared.global [%0], [%1], 16;" :: "r"(ds), "l"(src));
            }
            asm volatile("cp.async.commit_group;" ::: "memory");
        }

        // ===== phase 1: h-slice projections -> transposed global partials =====
        {
            float acc = 0.f;
#pragma unroll
            for (int i = 0; i < 32; i++) acc = fmaf(s_hl[i], wc[i], acc);
            __stcg(&g_pc[t * NC + j], acc);
        }
        if (t < MB) {
            float a = 0.f;
#pragma unroll
            for (int i = 0; i < 32; i++) a = fmaf(s_wrp[t][i], s_hl[i], a);
            __stcg(&g_rpp[t * NC + j], a);
        } else if (t < 2 * MB) {
            const int k = t - MB;
            float a = 0.f;
#pragma unroll
            for (int i = 0; i < 32; i++) a = fmaf(s_wwp[k][i], s_hl[i], a);
            __stcg(&g_wpp[k * NC + j], a);
        } else if (t == 200) {
            float a = 0.f;
#pragma unroll
            for (int i = 0; i < 32; i++) a = fmaf(s_wrg[i], s_hl[i], a);
            __stcg(&g_rgp[j], a);
        } else if (t == 201) {
            float a = 0.f;
#pragma unroll
            for (int i = 0; i < 32; i++) a = fmaf(s_wwg[i], s_hl[i], a);
            __stcg(&g_wgp[j], a);
        }
        __syncthreads();
        if (t == 0) { __threadfence(); __stcg(&g_flagA[j], tag); }

        // ensure prefetch of step s (committed last iter / prologue) landed
        asm volatile("cp.async.wait_group 1;" ::: "memory");

        // ----- barrier A: wait all CTAs' phase-1 partials -----
        if (t < NC) {
            while ((int)(*(volatile unsigned*)&g_flagA[t] - tag) < 0) { }
            __threadfence();
        }
        __syncthreads();

        const float* px = s_px[cur];

        // ===== phase (a): reductions + pout h-part =====
        float acc_h = 0.f;
#pragma unroll
        for (int i = 0; i < 32; i++) acc_h = fmaf(s_hl[i], whh[i], acc_h);

        if (t < MB) {
            s_ar[t] = px[PX_RP + t] + red16_cg(&g_rpp[t * NC]);
        } else if (t < 2 * MB) {
            const int k = t - MB;
            s_aw[k] = px[PX_WP + k] + red16_cg(&g_wpp[k * NC]);
        } else if (t == 200) {
            s_g[0] = px[PX_RG] + red16_cg(g_rgp);
        } else if (t == 201) {
            s_g[1] = px[PX_WG] + red16_cg(g_wgp);
        } else if (t >= 256 && t < 288) {
            const int cl = t - 256;
            float a = px[cl] + red16_cg(&g_pc[(base + cl) * NC]);
            s_c[cl] = fmaxf(a, 0.f);
        }
        __syncthreads();

        // ===== phase (b): softmax-exp + gate folding =====
        if (t < 32) {                 // read attention: e's + go/sum folded
            float m = -INFINITY;
            for (int k = t; k < MB; k += 32) m = fmaxf(m, s_ar[k]);
#pragma unroll
            for (int o = 16; o; o >>= 1) m = fmaxf(m, __shfl_xor_sync(0xFFFFFFFFu, m, o));
            float ssum = 0.f;
            for (int k = t; k < MB; k += 32) { float e = __expf(s_ar[k] - m); s_ar[k] = e; ssum += e; }
#pragma unroll
            for (int o = 16; o; o >>= 1) ssum += __shfl_xor_sync(0xFFFFFFFFu, ssum, o);
            if (t == 0) s_g[2] = (1.f / (1.f + __expf(-s_g[0]))) / ssum;   // go / sum_r
        } else if (t < 64) {          // write attention
            const int l = t - 32;
            float m = -INFINITY;
            for (int k = l; k < MB; k += 32) m = fmaxf(m, s_aw[k]);
#pragma unroll
            for (int o = 16; o; o >>= 1) m = fmaxf(m, __shfl_xor_sync(0xFFFFFFFFu, m, o));
            float ssum = 0.f;
            for (int k = l; k < MB; k += 32) { float e = __expf(s_aw[k] - m); s_aw[k] = e; ssum += e; }
#pragma unroll
            for (int o = 16; o; o >>= 1) ssum += __shfl_xor_sync(0xFFFFFFFFu, ssum, o);
            if (l == 0) { s_g[3] = 1.f / (1.f + __expf(-s_g[1])); s_g[4] = 1.f / ssum; }
        }
        __syncthreads();

        // ===== phase (c): r partials, 4-way split of the 100-deep dot =====
        if (t < 128) {
            const int part = t >> 5, col = t & 31;
            const int m0 = part * 25;
            float a = 0.f;
#pragma unroll
            for (int m2 = 0; m2 < 25; m2++) a = fmaf(s_ar[m0 + m2], s_mem[m0 + m2][col], a);
            s_rp[part][col] = a;
        }
        __syncthreads();

        // ===== phase (d): finalize r (go/sum already folded in s_g[2]) =====
        if (t < 32)
            s_r[t] = s_g[2] * ((s_rp[0][t] + s_rp[1][t]) + (s_rp[2][t] + s_rp[3][t]));
        __syncthreads();

        // ===== phase (e): pout partial, flagB, then mem update (overlapped) =====
        {
            float po = acc_h;
            float po2 = 0.f;
#pragma unroll
            for (int i = 0; i < 16; i++) {
                po  = fmaf(s_r[2 * i],     wrh[2 * i],     po);
                po2 = fmaf(s_r[2 * i + 1], wrh[2 * i + 1], po2);
            }
            __stcg(&g_pout[t * NC + j], po + po2);
        }
        __syncthreads();
        if (t == 0) { __threadfence(); __stcg(&g_flagB[j], tag); }

        // memory write (local; overlaps other CTAs' phase-(e))
        {
            const float gw = s_g[3], invw = s_g[4];
#pragma unroll
            for (int it = 0; it < 7; it++) {
                int idx = t + it * 512;
                if (idx < MB * 32) {
                    const int m2 = idx >> 5, cl = idx & 31;
                    const float aw = s_aw[m2] * invw;
                    s_mem[m2][cl] = gw * aw * s_c[cl] + (1.f - aw) * s_mem[m2][cl];
                }
            }
        }

        // ----- barrier B -----
        if (t < NC) {
            while ((int)(*(volatile unsigned*)&g_flagB[t] - tag) < 0) { }
            __threadfence();
        }
        __syncthreads();

        // ===== phase 3: reduce pout for OUR 32 columns only =====
        if (t < 32) {
            const int c = base + t;
            float hn = px[PX_H + t] + red16_cg(&g_pout[c * NC]);
            hn = fmaxf(hn, 0.f);
            out[(size_t)s * H + c] = hn;
            s_hl[t] = hn;
        }
        __syncthreads();
    }
}

// ---------------- launcher ----------------
extern "C" void kernel_launch(void* const* d_in, const int* in_sizes, int n_in,
                              void* d_out, int out_size) {
    const float* X    = (const float*)d_in[0];
    const float* Wc   = (const float*)d_in[1];
    const float* bc   = (const float*)d_in[2];
    const float* Wwg  = (const float*)d_in[3];
    const float* bwg  = (const float*)d_in[4];
    const float* Wwp  = (const float*)d_in[5];
    const float* bwp  = (const float*)d_in[6];
    const float* Wrg  = (const float*)d_in[7];
    const float* brg  = (const float*)d_in[8];
    const float* Wrp  = (const float*)d_in[9];
    const float* brp  = (const float*)d_in[10];
    const float* Wxh  = (const float*)d_in[11];
    const float* Wrh  = (const float*)d_in[12];
    const float* Whh  = (const float*)d_in[13];
    const float* bh   = (const float*)d_in[14];
    const int*   nImg = (const int*)d_in[15];

    prep_kernel<<<(ISZ * STRIDE + 255) / 256, 256>>>(Wc, bc, Wwg, bwg, Wwp, bwp,
                                                     Wrg, brg, Wrp, brp, Wxh, bh);
    dim3 ggrid(NSTEPS_MAX / 128, STRIDE / 64);
    gemm_kernel<<<ggrid, 256>>>(X);
    recur_kernel<<<NC, 512>>>(Wc, Wrg, Wrp, Wwg, Wwp, Wrh, Whh, (float*)d_out, nImg);
}

// round 11
// speedup vs baseline: 1.4803x; 1.2831x over previous
#include <cuda_runtime.h>
#include <cuda_bf16.h>
#include <math.h>
#include <stdint.h>

// Problem constants
#define NSTEPS_MAX 32768
#define ISZ 1024
#define H   512
#define MB  100

// Px layout (per-step precomputed x-projections + biases), padded stride
#define STRIDE 1280
#define OFF_C  0      // 512: x@Wc_x + bc
#define OFF_WG 512    // 1  : x@Wwg_x + bwg
#define OFF_WP 516    // 100: x@Wwp_x + bwp
#define OFF_RG 616    // 1
#define OFF_RP 620    // 100
#define OFF_H  720    // 512: x@Wxh + bh

#define NC 16         // CTAs in recurrence kernel
#define PSTR 128      // padded stride for MB-sized partial blocks

// ---------------- device global scratch (no runtime alloc allowed) ----------------
__device__ float g_Px[(size_t)NSTEPS_MAX * STRIDE];   // ~168 MB
__device__ float g_Wcat[(size_t)ISZ * STRIDE];        // 5.2 MB
__device__ float g_bcat[STRIDE];

// partials: PRODUCER-COALESCED layout [cta][elem] (writes = few lines; reads strided w/ MLP)
__device__ __align__(16) float g_pc[NC * H];
__device__ __align__(16) float g_rpp[NC * PSTR];
__device__ __align__(16) float g_wpp[NC * PSTR];
__device__ __align__(16) float g_rgp[NC];
__device__ __align__(16) float g_wgp[NC];
__device__ __align__(16) float g_pout[NC * H];

__device__ unsigned g_flagA[NC];   // monotonic step tags (zero-init at load)
__device__ unsigned g_flagB[NC];

// ---------------- scoped release/acquire flag ops ----------------
__device__ __forceinline__ void st_release_gpu(unsigned* p, unsigned v) {
    asm volatile("st.release.gpu.global.u32 [%0], %1;" :: "l"(p), "r"(v) : "memory");
}
__device__ __forceinline__ unsigned ld_acquire_gpu(const unsigned* p) {
    unsigned v;
    asm volatile("ld.acquire.gpu.global.u32 %0, [%1];" : "=r"(v) : "l"(p) : "memory");
    return v;
}

// ---------------- kernel 1: build concatenated weight/bias ----------------
__global__ void prep_kernel(const float* __restrict__ Wc,  const float* __restrict__ bc,
                            const float* __restrict__ Wwg, const float* __restrict__ bwg,
                            const float* __restrict__ Wwp, const float* __restrict__ bwp,
                            const float* __restrict__ Wrg, const float* __restrict__ brg,
                            const float* __restrict__ Wrp, const float* __restrict__ brp,
                            const float* __restrict__ Wxh, const float* __restrict__ bh) {
    int idx = blockIdx.x * blockDim.x + threadIdx.x;
    if (idx < ISZ * STRIDE) {
        int k = idx / STRIDE, n = idx % STRIDE;
        float v = 0.f;
        if (n < 512)                          v = Wc[(size_t)k * H + n];
        else if (n == OFF_WG)                 v = Wwg[k];
        else if (n >= OFF_WP && n < OFF_WP + MB) v = Wwp[(size_t)k * MB + (n - OFF_WP)];
        else if (n == OFF_RG)                 v = Wrg[k];
        else if (n >= OFF_RP && n < OFF_RP + MB) v = Wrp[(size_t)k * MB + (n - OFF_RP)];
        else if (n >= OFF_H && n < OFF_H + H) v = Wxh[(size_t)k * H + (n - OFF_H)];
        g_Wcat[idx] = v;
    }
    if (idx < STRIDE) {
        int n = idx;
        float b = 0.f;
        if (n < 512)                          b = bc[n];
        else if (n == OFF_WG)                 b = bwg[0];
        else if (n >= OFF_WP && n < OFF_WP + MB) b = bwp[n - OFF_WP];
        else if (n == OFF_RG)                 b = brg[0];
        else if (n >= OFF_RP && n < OFF_RP + MB) b = brp[n - OFF_RP];
        else if (n >= OFF_H && n < OFF_H + H) b = bh[n - OFF_H];
        g_bcat[n] = b;
    }
}

// ---------------- kernel 2: Px = X @ Wcat + bcat (tiled fp32 GEMM) ----------------
__global__ void __launch_bounds__(256) gemm_kernel(const float* __restrict__ X) {
    __shared__ float As[16][128];
    __shared__ float Bs[16][64];

    const int tid = threadIdx.x;
    const int bm = blockIdx.x * 128;
    const int bn = blockIdx.y * 64;

    const int ty = tid >> 4;
    const int tx = tid & 15;

    float acc[8][4];
#pragma unroll
    for (int i = 0; i < 8; i++)
#pragma unroll
        for (int j = 0; j < 4; j++) acc[i][j] = 0.f;

    const int a_m = tid >> 2;
    const int a_k = (tid & 3) * 4;
    const int b_k = tid >> 4;
    const int b_n = (tid & 15) * 4;

    for (int k0 = 0; k0 < ISZ; k0 += 16) {
        float4 v0 = *reinterpret_cast<const float4*>(&X[(size_t)(bm + a_m) * ISZ + k0 + a_k]);
        float4 v1 = *reinterpret_cast<const float4*>(&X[(size_t)(bm + a_m + 64) * ISZ + k0 + a_k]);
        float4 w  = *reinterpret_cast<const float4*>(&g_Wcat[(size_t)(k0 + b_k) * STRIDE + bn + b_n]);
        As[a_k + 0][a_m] = v0.x; As[a_k + 1][a_m] = v0.y;
        As[a_k + 2][a_m] = v0.z; As[a_k + 3][a_m] = v0.w;
        As[a_k + 0][a_m + 64] = v1.x; As[a_k + 1][a_m + 64] = v1.y;
        As[a_k + 2][a_m + 64] = v1.z; As[a_k + 3][a_m + 64] = v1.w;
        *reinterpret_cast<float4*>(&Bs[b_k][b_n]) = w;
        __syncthreads();
#pragma unroll
        for (int kk = 0; kk < 16; kk++) {
            float a[8], b[4];
#pragma unroll
            for (int i = 0; i < 8; i++) a[i] = As[kk][ty * 8 + i];
#pragma unroll
            for (int j = 0; j < 4; j++) b[j] = Bs[kk][tx * 4 + j];
#pragma unroll
            for (int i = 0; i < 8; i++)
#pragma unroll
                for (int j = 0; j < 4; j++) acc[i][j] = fmaf(a[i], b[j], acc[i][j]);
        }
        __syncthreads();
    }
#pragma unroll
    for (int i = 0; i < 8; i++) {
        int row = bm + ty * 8 + i;
        int col = bn + tx * 4;
        float4 o;
        o.x = acc[i][0] + g_bcat[col + 0];
        o.y = acc[i][1] + g_bcat[col + 1];
        o.z = acc[i][2] + g_bcat[col + 2];
        o.w = acc[i][3] + g_bcat[col + 3];
        *reinterpret_cast<float4*>(&g_Px[(size_t)row * STRIDE + col]) = o;
    }
}

// ---------------- helpers ----------------
// strided 16-way reduction, all loads independent (MLP 16)
__device__ __forceinline__ float redS(const float* p, int stride) {
    float v[16];
#pragma unroll
    for (int k = 0; k < 16; k++) v[k] = __ldcg(p + k * stride);
    float s0 = (v[0] + v[1]) + (v[2] + v[3]);
    float s1 = (v[4] + v[5]) + (v[6] + v[7]);
    float s2 = (v[8] + v[9]) + (v[10] + v[11]);
    float s3 = (v[12] + v[13]) + (v[14] + v[15]);
    return (s0 + s1) + (s2 + s3);
}
// contiguous 16-way reduction (for the scalar gate partial arrays)
__device__ __forceinline__ float red16_cg(const float* p) {
    float4 a = __ldcg((const float4*)(p + 0));
    float4 b = __ldcg((const float4*)(p + 4));
    float4 c = __ldcg((const float4*)(p + 8));
    float4 d = __ldcg((const float4*)(p + 12));
    return ((a.x + a.y) + (a.z + a.w)) + ((b.x + b.y) + (b.z + b.w))
         + ((c.x + c.y) + (c.z + c.w)) + ((d.x + d.y) + (d.z + d.w));
}

__device__ __forceinline__ void bar_named(int id, int cnt) {
    asm volatile("bar.sync %0, %1;" :: "r"(id), "r"(cnt) : "memory");
}

// SMEM px tile layout (272 floats):
//   [0..32)    : C slice (cols base..base+32)
//   [32..240)  : mid block g_Px[512..720): WG@32, WP@36+k, RG@136, RP@140+k
//   [240..272) : H slice (cols base..base+32)
#define PX_WG 32
#define PX_WP 36
#define PX_RG 136
#define PX_RP 140
#define PX_H  240

// ---------------- kernel 3: sequential recurrence (16 CTAs x 512 threads) ----------------
__global__ void __launch_bounds__(512, 1) recur_kernel(
    const float* __restrict__ Wc,  const float* __restrict__ Wrg,
    const float* __restrict__ Wrp, const float* __restrict__ Wwg,
    const float* __restrict__ Wwp, const float* __restrict__ Wrh,
    const float* __restrict__ Whh, float* __restrict__ out,
    const int* __restrict__ nImgP) {

    __shared__ float s_hl[32];              // this CTA's h slice
    __shared__ float s_wrp[MB][33];
    __shared__ float s_wwp[MB][33];
    __shared__ float s_wrg[32];
    __shared__ float s_wwg[32];
    __shared__ float s_mem[MB][33];
    __shared__ float s_ar[MB];              // unnormalized exp(e_r)
    __shared__ float s_aw[MB];              // unnormalized exp(e_w)
    __shared__ float s_c[32];
    __shared__ float s_r[32];
    __shared__ float s_rp[4][33];
    __shared__ float s_g[8];   // 0=rg logit 1=wg logit 2=go/sum_r 3=gw 4=inv_sum_w
    __shared__ __align__(16) float s_px[2][272];
    __shared__ unsigned s_base;

    const int t = threadIdx.x;
    const int j = blockIdx.x;
    const int base = j * 32;

    // register-resident weight columns: thread t owns output column t
    float wc[32], whh[32], wrh[32];
#pragma unroll
    for (int i = 0; i < 32; i++) {
        wc[i]  = Wc[(size_t)(ISZ + base + i) * H + t];
        whh[i] = Whh[(size_t)(base + i) * H + t];
        wrh[i] = Wrh[(size_t)(base + i) * H + t];
    }
    for (int idx = t; idx < MB * 32; idx += 512) {
        int k = idx >> 5, i = idx & 31;
        s_wrp[k][i] = Wrp[(size_t)(ISZ + base + i) * MB + k];
        s_wwp[k][i] = Wwp[(size_t)(ISZ + base + i) * MB + k];
    }
    if (t < 32) { s_wrg[t] = Wrg[ISZ + base + t]; s_wwg[t] = Wwg[ISZ + base + t]; }
    for (int idx = t; idx < MB * 33; idx += 512) ((float*)s_mem)[idx] = 0.f;
    if (t < 32) s_hl[t] = 0.f;
    if (t == 0) s_base = *(volatile unsigned*)&g_flagA[j];   // replay-safe tag base
    __syncthreads();

    int nSteps = *nImgP;
    if (nSteps > NSTEPS_MAX) nSteps = NSTEPS_MAX;
    if (nSteps <= 0) return;
    const unsigned tag0 = s_base;

    // --- prologue prefetch: step 0 into buffer 0 ---
    {
        const float* row = g_Px;
        if (t < 68) {
            const float* src; float* dst;
            if (t < 8)       { src = row + OFF_C + base + t * 4;        dst = &s_px[0][t * 4]; }
            else if (t < 60) { src = row + 512 + (t - 8) * 4;           dst = &s_px[0][32 + (t - 8) * 4]; }
            else             { src = row + OFF_H + base + (t - 60) * 4; dst = &s_px[0][240 + (t - 60) * 4]; }
            unsigned ds = (unsigned)__cvta_generic_to_shared(dst);
            asm volatile("cp.async.cg.shared.global [%0], [%1], 16;" :: "r"(ds), "l"(src));
        }
        asm volatile("cp.async.commit_group;" ::: "memory");
    }

    for (int s = 0; s < nSteps; s++) {
        const int cur = s & 1;
        const unsigned tag = tag0 + (unsigned)s + 1u;

        // --- prefetch step s+1 into other buffer ---
        {
            int sp = s + 1; if (sp >= nSteps) sp = nSteps - 1;
            const float* row = g_Px + (size_t)sp * STRIDE;
            if (t < 68) {
                const float* src; float* dst;
                if (t < 8)       { src = row + OFF_C + base + t * 4;        dst = &s_px[cur ^ 1][t * 4]; }
                else if (t < 60) { src = row + 512 + (t - 8) * 4;           dst = &s_px[cur ^ 1][32 + (t - 8) * 4]; }
                else             { src = row + OFF_H + base + (t - 60) * 4; dst = &s_px[cur ^ 1][240 + (t - 60) * 4]; }
                unsigned ds = (unsigned)__cvta_generic_to_shared(dst);
                asm volatile("cp.async.cg.shared.global [%0], [%1], 16;" :: "r"(ds), "l"(src));
            }
            asm volatile("cp.async.commit_group;" ::: "memory");
        }

        // ===== phase 1: h-slice projections -> COALESCED global partials =====
        {
            float acc = 0.f;
#pragma unroll
            for (int i = 0; i < 32; i++) acc = fmaf(s_hl[i], wc[i], acc);
            __stcg(&g_pc[j * H + t], acc);
        }
        if (t < MB) {
            float a = 0.f;
#pragma unroll
            for (int i = 0; i < 32; i++) a = fmaf(s_wrp[t][i], s_hl[i], a);
            __stcg(&g_rpp[j * PSTR + t], a);
        } else if (t < 2 * MB) {
            const int k = t - MB;
            float a = 0.f;
#pragma unroll
            for (int i = 0; i < 32; i++) a = fmaf(s_wwp[k][i], s_hl[i], a);
            __stcg(&g_wpp[j * PSTR + k], a);
        } else if (t == 200) {
            float a = 0.f;
#pragma unroll
            for (int i = 0; i < 32; i++) a = fmaf(s_wrg[i], s_hl[i], a);
            __stcg(&g_rgp[j], a);
        } else if (t == 201) {
            float a = 0.f;
#pragma unroll
            for (int i = 0; i < 32; i++) a = fmaf(s_wwg[i], s_hl[i], a);
            __stcg(&g_wgp[j], a);
        }

        // off-critical-path precompute while stores drain: h-part of pout
        float acc_h = 0.f;
#pragma unroll
        for (int i = 0; i < 32; i++) acc_h = fmaf(s_hl[i], whh[i], acc_h);

        __syncthreads();                                  // S1
        if (t == 0) st_release_gpu(&g_flagA[j], tag);     // release: prior stores visible

        // ensure prefetch of step s landed
        asm volatile("cp.async.wait_group 1;" ::: "memory");

        // ----- barrier A: wait all CTAs' phase-1 partials -----
        if (t < NC) {
            while ((int)(ld_acquire_gpu(&g_flagA[t]) - tag) < 0) { }
        }
        __syncthreads();                                  // S2

        const float* px = s_px[cur];

        // ===== phase (a): partial reductions, split by barrier group =====
        // group A (warps 0-3, t<128): read-attention path (critical)
        // group B (warps 4-7, t in [128,256)): write-attention path
        // group C (warp 8): c slice
        if (t < 128) {
            if (t < MB) {
                s_ar[t] = px[PX_RP + t] + redS(&g_rpp[t], PSTR);
            } else if (t == MB) {
                s_g[0] = px[PX_RG] + red16_cg(g_rgp);
            }
            bar_named(1, 128);
            // warp 0: softmax-exp over ar, fold go/sum into s_g[2]
            if (t < 32) {
                float m = -INFINITY;
                for (int k = t; k < MB; k += 32) m = fmaxf(m, s_ar[k]);
#pragma unroll
                for (int o = 16; o; o >>= 1) m = fmaxf(m, __shfl_xor_sync(0xFFFFFFFFu, m, o));
                float ssum = 0.f;
                for (int k = t; k < MB; k += 32) { float e = __expf(s_ar[k] - m); s_ar[k] = e; ssum += e; }
#pragma unroll
                for (int o = 16; o; o >>= 1) ssum += __shfl_xor_sync(0xFFFFFFFFu, ssum, o);
                if (t == 0) s_g[2] = (1.f / (1.f + __expf(-s_g[0]))) / ssum;   // go / sum_r
            }
            bar_named(1, 128);
            // warps 0-3: 4-way split of ar @ mem
            {
                const int part = t >> 5, col = t & 31;
                const int m0 = part * 25;
                float a = 0.f;
#pragma unroll
                for (int m2 = 0; m2 < 25; m2++) a = fmaf(s_ar[m0 + m2], s_mem[m0 + m2][col], a);
                s_rp[part][col] = a;
            }
            bar_named(1, 128);
            if (t < 32)
                s_r[t] = s_g[2] * ((s_rp[0][t] + s_rp[1][t]) + (s_rp[2][t] + s_rp[3][t]));
        } else if (t < 256) {
            const int k = t - 128;
            if (k < MB) {
                s_aw[k] = px[PX_WP + k] + redS(&g_wpp[k], PSTR);
            } else if (k == MB) {
                s_g[1] = px[PX_WG] + red16_cg(g_wgp);
            }
            bar_named(2, 128);
            // warp 4: softmax-exp over aw
            if (k < 32) {
                float m = -INFINITY;
                for (int q = k; q < MB; q += 32) m = fmaxf(m, s_aw[q]);
#pragma unroll
                for (int o = 16; o; o >>= 1) m = fmaxf(m, __shfl_xor_sync(0xFFFFFFFFu, m, o));
                float ssum = 0.f;
                for (int q = k; q < MB; q += 32) { float e = __expf(s_aw[q] - m); s_aw[q] = e; ssum += e; }
#pragma unroll
                for (int o = 16; o; o >>= 1) ssum += __shfl_xor_sync(0xFFFFFFFFu, ssum, o);
                if (k == 0) { s_g[3] = 1.f / (1.f + __expf(-s_g[1])); s_g[4] = 1.f / ssum; }
            }
        } else if (t < 288) {
            const int cl = t - 256;
            float a = px[cl] + redS(&g_pc[base + cl], H);
            s_c[cl] = fmaxf(a, 0.f);
        }
        __syncthreads();                                  // S5 (s_r, s_aw, s_c, s_g ready)

        // ===== pout partial: acc_h + r_slice @ Wrh, coalesced store =====
        {
            float po = acc_h;
            float po2 = 0.f;
#pragma unroll
            for (int i = 0; i < 16; i++) {
                po  = fmaf(s_r[2 * i],     wrh[2 * i],     po);
                po2 = fmaf(s_r[2 * i + 1], wrh[2 * i + 1], po2);
            }
            __stcg(&g_pout[j * H + t], po + po2);
        }
        __syncthreads();                                  // S6
        if (t == 0) st_release_gpu(&g_flagB[j], tag);

        // memory write (local; overlaps pollB window)
        {
            const float gw = s_g[3], invw = s_g[4];
#pragma unroll
            for (int it = 0; it < 7; it++) {
                int idx = t + it * 512;
                if (idx < MB * 32) {
                    const int m2 = idx >> 5, cl = idx & 31;
                    const float aw = s_aw[m2] * invw;
                    s_mem[m2][cl] = gw * aw * s_c[cl] + (1.f - aw) * s_mem[m2][cl];
                }
            }
        }

        // ----- barrier B -----
        if (t < NC) {
            while ((int)(ld_acquire_gpu(&g_flagB[t]) - tag) < 0) { }
        }
        __syncthreads();                                  // S7

        // ===== phase 3: reduce pout for OUR 32 columns only =====
        if (t < 32) {
            const int c = base + t;
            float hn = px[PX_H + t] + redS(&g_pout[c], H);
            hn = fmaxf(hn, 0.f);
            out[(size_t)s * H + c] = hn;
            s_hl[t] = hn;
        }
        __syncthreads();                                  // S8
    }
}

// ---------------- launcher ----------------
extern "C" void kernel_launch(void* const* d_in, const int* in_sizes, int n_in,
                              void* d_out, int out_size) {
    const float* X    = (const float*)d_in[0];
    const float* Wc   = (const float*)d_in[1];
    const float* bc   = (const float*)d_in[2];
    const float* Wwg  = (const float*)d_in[3];
    const float* bwg  = (const float*)d_in[4];
    const float* Wwp  = (const float*)d_in[5];
    const float* bwp  = (const float*)d_in[6];
    const float* Wrg  = (const float*)d_in[7];
    const float* brg  = (const float*)d_in[8];
    const float* Wrp  = (const float*)d_in[9];
    const float* brp  = (const float*)d_in[10];
    const float* Wxh  = (const float*)d_in[11];
    const float* Wrh  = (const float*)d_in[12];
    const float* Whh  = (const float*)d_in[13];
    const float* bh   = (const float*)d_in[14];
    const int*   nImg = (const int*)d_in[15];

    prep_kernel<<<(ISZ * STRIDE + 255) / 256, 256>>>(Wc, bc, Wwg, bwg, Wwp, bwp,
                                                     Wrg, brg, Wrp, brp, Wxh, bh);
    dim3 ggrid(NSTEPS_MAX / 128, STRIDE / 64);
    gemm_kernel<<<ggrid, 256>>>(X);
    recur_kernel<<<NC, 512>>>(Wc, Wrg, Wrp, Wwg, Wwp, Wrh, Whh, (float*)d_out, nImg);
}

// round 14
// speedup vs baseline: 1.7677x; 1.1941x over previous
#include <cuda_runtime.h>
#include <cuda_bf16.h>
#include <math.h>
#include <stdint.h>

// Problem constants
#define NSTEPS_MAX 32768
#define ISZ 1024
#define H   512
#define MB  100

// Px layout (per-step precomputed x-projections + biases), padded stride
#define STRIDE 1280
#define OFF_C  0      // 512: x@Wc_x + bc
#define OFF_WG 512    // 1  : x@Wwg_x + bwg
#define OFF_WP 516    // 100: x@Wwp_x + bwp
#define OFF_RG 616    // 1
#define OFF_RP 620    // 100
#define OFF_H  720    // 512: x@Wxh + bh

#define NC 16         // CTAs in recurrence kernel (one cluster)
#define PSTR 128      // padded stride for MB-sized partial blocks

// ---------------- device global scratch (no runtime alloc allowed) ----------------
__device__ float g_Px[(size_t)NSTEPS_MAX * STRIDE];   // ~168 MB
__device__ float g_Wcat[(size_t)ISZ * STRIDE];        // 5.2 MB
__device__ float g_bcat[STRIDE];

// all-to-all partials stay in L2: producer-coalesced layout [cta][elem]
__device__ __align__(16) float g_rpp[NC * PSTR];
__device__ __align__(16) float g_wpp[NC * PSTR];
__device__ __align__(16) float g_rgp[NC];
__device__ __align__(16) float g_wgp[NC];

// ---------------- PTX helpers ----------------
__device__ __forceinline__ uint32_t smem_u32(const void* p) {
    return (uint32_t)__cvta_generic_to_shared(p);
}
__device__ __forceinline__ void mbar_init(uint32_t addr, uint32_t cnt) {
    asm volatile("mbarrier.init.shared.b64 [%0], %1;" :: "r"(addr), "r"(cnt) : "memory");
}
// remote store of one float into peer CTA's SMEM
__device__ __forceinline__ void st_remote_f32(uint32_t laddr, uint32_t rank, float v) {
    uint32_t r;
    asm volatile("mapa.shared::cluster.u32 %0, %1, %2;" : "=r"(r) : "r"(laddr), "r"(rank));
    asm volatile("st.shared::cluster.f32 [%0], %1;" :: "r"(r), "f"(v) : "memory");
}
// remote mbarrier arrive with cluster-scope release (cumulative)
__device__ __forceinline__ void arrive_remote(uint32_t laddr, uint32_t rank) {
    uint32_t r;
    asm volatile("mapa.shared::cluster.u32 %0, %1, %2;" : "=r"(r) : "r"(laddr), "r"(rank));
    asm volatile("mbarrier.arrive.release.cluster.shared::cluster.b64 _, [%0];" :: "r"(r) : "memory");
}
// parity wait with cluster-scope acquire
__device__ __forceinline__ void wait_parity_cluster(uint32_t addr, uint32_t parity) {
    uint32_t done;
    asm volatile(
        "{\n\t.reg .pred p;\n\t"
        "mbarrier.try_wait.parity.acquire.cluster.shared::cta.b64 p, [%1], %2;\n\t"
        "selp.b32 %0, 1, 0, p;\n\t}"
        : "=r"(done) : "r"(addr), "r"(parity) : "memory");
    if (!done) {
        asm volatile(
            "{\n\t.reg .pred P1;\n\t"
            "WAIT_LOOP_%=:\n\t"
            "mbarrier.try_wait.parity.acquire.cluster.shared::cta.b64 P1, [%0], %1, 0x989680;\n\t"
            "@P1 bra.uni WAIT_DONE_%=;\n\t"
            "bra.uni WAIT_LOOP_%=;\n\t"
            "WAIT_DONE_%=:\n\t}"
            :: "r"(addr), "r"(parity) : "memory");
    }
}
__device__ __forceinline__ void cluster_sync_all() {
    asm volatile("barrier.cluster.arrive.aligned;" ::: "memory");
    asm volatile("barrier.cluster.wait.aligned;" ::: "memory");
}
__device__ __forceinline__ void bar_named(int id, int cnt) {
    asm volatile("bar.sync %0, %1;" :: "r"(id), "r"(cnt) : "memory");
}

// ---------------- kernel 1: build concatenated weight/bias ----------------
__global__ void prep_kernel(const float* __restrict__ Wc,  const float* __restrict__ bc,
                            const float* __restrict__ Wwg, const float* __restrict__ bwg,
                            const float* __restrict__ Wwp, const float* __restrict__ bwp,
                            const float* __restrict__ Wrg, const float* __restrict__ brg,
                            const float* __restrict__ Wrp, const float* __restrict__ brp,
                            const float* __restrict__ Wxh, const float* __restrict__ bh) {
    int idx = blockIdx.x * blockDim.x + threadIdx.x;
    if (idx < ISZ * STRIDE) {
        int k = idx / STRIDE, n = idx % STRIDE;
        float v = 0.f;
        if (n < 512)                          v = Wc[(size_t)k * H + n];
        else if (n == OFF_WG)                 v = Wwg[k];
        else if (n >= OFF_WP && n < OFF_WP + MB) v = Wwp[(size_t)k * MB + (n - OFF_WP)];
        else if (n == OFF_RG)                 v = Wrg[k];
        else if (n >= OFF_RP && n < OFF_RP + MB) v = Wrp[(size_t)k * MB + (n - OFF_RP)];
        else if (n >= OFF_H && n < OFF_H + H) v = Wxh[(size_t)k * H + (n - OFF_H)];
        g_Wcat[idx] = v;
    }
    if (idx < STRIDE) {
        int n = idx;
        float b = 0.f;
        if (n < 512)                          b = bc[n];
        else if (n == OFF_WG)                 b = bwg[0];
        else if (n >= OFF_WP && n < OFF_WP + MB) b = bwp[n - OFF_WP];
        else if (n == OFF_RG)                 b = brg[0];
        else if (n >= OFF_RP && n < OFF_RP + MB) b = brp[n - OFF_RP];
        else if (n >= OFF_H && n < OFF_H + H) b = bh[n - OFF_H];
        g_bcat[n] = b;
    }
}

// ---------------- kernel 2: Px = X @ Wcat + bcat (tiled fp32 GEMM) ----------------
__global__ void __launch_bounds__(256) gemm_kernel(const float* __restrict__ X) {
    __shared__ float As[16][128];
    __shared__ float Bs[16][64];

    const int tid = threadIdx.x;
    const int bm = blockIdx.x * 128;
    const int bn = blockIdx.y * 64;

    const int ty = tid >> 4;
    const int tx = tid & 15;

    float acc[8][4];
#pragma unroll
    for (int i = 0; i < 8; i++)
#pragma unroll
        for (int j = 0; j < 4; j++) acc[i][j] = 0.f;

    const int a_m = tid >> 2;
    const int a_k = (tid & 3) * 4;
    const int b_k = tid >> 4;
    const int b_n = (tid & 15) * 4;

    for (int k0 = 0; k0 < ISZ; k0 += 16) {
        float4 v0 = *reinterpret_cast<const float4*>(&X[(size_t)(bm + a_m) * ISZ + k0 + a_k]);
        float4 v1 = *reinterpret_cast<const float4*>(&X[(size_t)(bm + a_m + 64) * ISZ + k0 + a_k]);
        float4 w  = *reinterpret_cast<const float4*>(&g_Wcat[(size_t)(k0 + b_k) * STRIDE + bn + b_n]);
        As[a_k + 0][a_m] = v0.x; As[a_k + 1][a_m] = v0.y;
        As[a_k + 2][a_m] = v0.z; As[a_k + 3][a_m] = v0.w;
        As[a_k + 0][a_m + 64] = v1.x; As[a_k + 1][a_m + 64] = v1.y;
        As[a_k + 2][a_m + 64] = v1.z; As[a_k + 3][a_m + 64] = v1.w;
        *reinterpret_cast<float4*>(&Bs[b_k][b_n]) = w;
        __syncthreads();
#pragma unroll
        for (int kk = 0; kk < 16; kk++) {
            float a[8], b[4];
#pragma unroll
            for (int i = 0; i < 8; i++) a[i] = As[kk][ty * 8 + i];
#pragma unroll
            for (int j = 0; j < 4; j++) b[j] = Bs[kk][tx * 4 + j];
#pragma unroll
            for (int i = 0; i < 8; i++)
#pragma unroll
                for (int j = 0; j < 4; j++) acc[i][j] = fmaf(a[i], b[j], acc[i][j]);
        }
        __syncthreads();
    }
#pragma unroll
    for (int i = 0; i < 8; i++) {
        int row = bm + ty * 8 + i;
        int col = bn + tx * 4;
        float4 o;
        o.x = acc[i][0] + g_bcat[col + 0];
        o.y = acc[i][1] + g_bcat[col + 1];
        o.z = acc[i][2] + g_bcat[col + 2];
        o.w = acc[i][3] + g_bcat[col + 3];
        *reinterpret_cast<float4*>(&g_Px[(size_t)row * STRIDE + col]) = o;
    }
}

// ---------------- reduction helpers ----------------
__device__ __forceinline__ float redS(const float* p, int stride) {
    float v[16];
#pragma unroll
    for (int k = 0; k < 16; k++) v[k] = __ldcg(p + k * stride);
    float s0 = (v[0] + v[1]) + (v[2] + v[3]);
    float s1 = (v[4] + v[5]) + (v[6] + v[7]);
    float s2 = (v[8] + v[9]) + (v[10] + v[11]);
    float s3 = (v[12] + v[13]) + (v[14] + v[15]);
    return (s0 + s1) + (s2 + s3);
}
__device__ __forceinline__ float red16_cg(const float* p) {
    float4 a = __ldcg((const float4*)(p + 0));
    float4 b = __ldcg((const float4*)(p + 4));
    float4 c = __ldcg((const float4*)(p + 8));
    float4 d = __ldcg((const float4*)(p + 12));
    return ((a.x + a.y) + (a.z + a.w)) + ((b.x + b.y) + (b.z + b.w))
         + ((c.x + c.y) + (c.z + c.w)) + ((d.x + d.y) + (d.z + d.w));
}

// SMEM px tile layout (272 floats)
#define PX_WG 32
#define PX_WP 36
#define PX_RG 136
#define PX_RP 140
#define PX_H  240

// ---------------- kernel 3: sequential recurrence (cluster of 16 CTAs x 512) ----------------
__global__ void __launch_bounds__(512, 1) recur_kernel(
    const float* __restrict__ Wc,  const float* __restrict__ Wrg,
    const float* __restrict__ Wrp, const float* __restrict__ Wwg,
    const float* __restrict__ Wwp, const float* __restrict__ Wrh,
    const float* __restrict__ Whh, float* __restrict__ out,
    const int* __restrict__ nImgP) {

    __shared__ float s_hl[32];
    __shared__ float s_wrp[MB][33];
    __shared__ float s_wwp[MB][33];
    __shared__ float s_wrg[32];
    __shared__ float s_wwg[32];
    __shared__ float s_mem[MB][33];
    __shared__ float s_ar[MB];
    __shared__ float s_aw[MB];
    __shared__ float s_c[32];
    __shared__ float s_r[32];
    __shared__ float s_rp[4][33];
    __shared__ float s_g[8];   // 0=rg logit 1=wg logit 2=go/sum_r 3=gw 4=inv_sum_w
    __shared__ __align__(16) float s_px[2][272];
    __shared__ float s_bufpc[NC][32];     // DSMEM-scattered pc window
    __shared__ float s_bufpout[NC][32];   // DSMEM-scattered pout window
    __shared__ __align__(8) unsigned long long s_mbar[2];  // [0]=A, [1]=B

    const int t = threadIdx.x;
    const int j = blockIdx.x;
    const int base = j * 32;

    const uint32_t mbarA = smem_u32(&s_mbar[0]);
    const uint32_t mbarB = smem_u32(&s_mbar[1]);

    // register-resident weight columns: thread t owns output column t
    float wc[32], whh[32], wrh[32];
#pragma unroll
    for (int i = 0; i < 32; i++) {
        wc[i]  = Wc[(size_t)(ISZ + base + i) * H + t];
        whh[i] = Whh[(size_t)(base + i) * H + t];
        wrh[i] = Wrh[(size_t)(base + i) * H + t];
    }
    for (int idx = t; idx < MB * 32; idx += 512) {
        int k = idx >> 5, i = idx & 31;
        s_wrp[k][i] = Wrp[(size_t)(ISZ + base + i) * MB + k];
        s_wwp[k][i] = Wwp[(size_t)(ISZ + base + i) * MB + k];
    }
    if (t < 32) { s_wrg[t] = Wrg[ISZ + base + t]; s_wwg[t] = Wwg[ISZ + base + t]; }
    for (int idx = t; idx < MB * 33; idx += 512) ((float*)s_mem)[idx] = 0.f;
    if (t < 32) s_hl[t] = 0.f;
    if (t == 0) { mbar_init(mbarA, NC); mbar_init(mbarB, NC); }
    __syncthreads();
    cluster_sync_all();   // all mbarriers initialized before any remote arrive

    int nSteps = *nImgP;
    if (nSteps > NSTEPS_MAX) nSteps = NSTEPS_MAX;
    if (nSteps <= 0) nSteps = 1;

    // --- prologue prefetch: step 0 into buffer 0 ---
    {
        const float* row = g_Px;
        if (t < 68) {
            const float* src; float* dst;
            if (t < 8)       { src = row + OFF_C + base + t * 4;        dst = &s_px[0][t * 4]; }
            else if (t < 60) { src = row + 512 + (t - 8) * 4;           dst = &s_px[0][32 + (t - 8) * 4]; }
            else             { src = row + OFF_H + base + (t - 60) * 4; dst = &s_px[0][240 + (t - 60) * 4]; }
            unsigned ds = (unsigned)__cvta_generic_to_shared(dst);
            asm volatile("cp.async.cg.shared.global [%0], [%1], 16;" :: "r"(ds), "l"(src));
        }
        asm volatile("cp.async.commit_group;" ::: "memory");
    }

    for (int s = 0; s < nSteps; s++) {
        const int cur = s & 1;
        const uint32_t parity = (uint32_t)(s & 1);

        // --- prefetch step s+1 into other buffer ---
        {
            int sp = s + 1; if (sp >= nSteps) sp = nSteps - 1;
            const float* row = g_Px + (size_t)sp * STRIDE;
            if (t < 68) {
                const float* src; float* dst;
                if (t < 8)       { src = row + OFF_C + base + t * 4;        dst = &s_px[cur ^ 1][t * 4]; }
                else if (t < 60) { src = row + 512 + (t - 8) * 4;           dst = &s_px[cur ^ 1][32 + (t - 8) * 4]; }
                else             { src = row + OFF_H + base + (t - 60) * 4; dst = &s_px[cur ^ 1][240 + (t - 60) * 4]; }
                unsigned ds = (unsigned)__cvta_generic_to_shared(dst);
                asm volatile("cp.async.cg.shared.global [%0], [%1], 16;" :: "r"(ds), "l"(src));
            }
            asm volatile("cp.async.commit_group;" ::: "memory");
        }

        // ===== phase 1: h-slice projections =====
        // pc column t -> DSMEM scatter into consumer (t>>5)'s window
        {
            float acc = 0.f;
#pragma unroll
            for (int i = 0; i < 32; i++) acc = fmaf(s_hl[i], wc[i], acc);
            st_remote_f32(smem_u32(&s_bufpc[j][t & 31]), (uint32_t)(t >> 5), acc);
        }
        // rpp/wpp/gates -> coalesced L2 (all-to-all payload)
        if (t < MB) {
            float a = 0.f;
#pragma unroll
            for (int i = 0; i < 32; i++) a = fmaf(s_wrp[t][i], s_hl[i], a);
            __stcg(&g_rpp[j * PSTR + t], a);
        } else if (t < 2 * MB) {
            const int k = t - MB;
            float a = 0.f;
#pragma unroll
            for (int i = 0; i < 32; i++) a = fmaf(s_wwp[k][i], s_hl[i], a);
            __stcg(&g_wpp[j * PSTR + k], a);
        } else if (t == 200) {
            float a = 0.f;
#pragma unroll
            for (int i = 0; i < 32; i++) a = fmaf(s_wrg[i], s_hl[i], a);
            __stcg(&g_rgp[j], a);
        } else if (t == 201) {
            float a = 0.f;
#pragma unroll
            for (int i = 0; i < 32; i++) a = fmaf(s_wwg[i], s_hl[i], a);
            __stcg(&g_wgp[j], a);
        }

        // off-critical-path precompute: h-part of pout
        float acc_h = 0.f;
#pragma unroll
        for (int i = 0; i < 32; i++) acc_h = fmaf(s_hl[i], whh[i], acc_h);

        __syncthreads();                                  // S1: all stores issued
        if (t < NC) arrive_remote(mbarA, (uint32_t)t);    // release.cluster (cumulative)

        // ensure prefetch of step s landed
        asm volatile("cp.async.wait_group 1;" ::: "memory");

        // ----- exchange A wait -----
        wait_parity_cluster(mbarA, parity);
        __syncthreads();                                  // S2: s_px visibility

        const float* px = s_px[cur];

        // ===== phase (a)/(b)/(c)/(d): attention path in barrier groups =====
        if (t < 128) {
            if (t < MB) {
                s_ar[t] = px[PX_RP + t] + redS(&g_rpp[t], PSTR);
            } else if (t == MB) {
                s_g[0] = px[PX_RG] + red16_cg(g_rgp);
            }
            bar_named(1, 128);
            if (t < 32) {
                float m = -INFINITY;
                for (int k = t; k < MB; k += 32) m = fmaxf(m, s_ar[k]);
#pragma unroll
                for (int o = 16; o; o >>= 1) m = fmaxf(m, __shfl_xor_sync(0xFFFFFFFFu, m, o));
                float ssum = 0.f;
                for (int k = t; k < MB; k += 32) { float e = __expf(s_ar[k] - m); s_ar[k] = e; ssum += e; }
#pragma unroll
                for (int o = 16; o; o >>= 1) ssum += __shfl_xor_sync(0xFFFFFFFFu, ssum, o);
                if (t == 0) s_g[2] = (1.f / (1.f + __expf(-s_g[0]))) / ssum;   // go / sum_r
            }
            bar_named(1, 128);
            {
                const int part = t >> 5, col = t & 31;
                const int m0 = part * 25;
                float a = 0.f;
#pragma unroll
                for (int m2 = 0; m2 < 25; m2++) a = fmaf(s_ar[m0 + m2], s_mem[m0 + m2][col], a);
                s_rp[part][col] = a;
            }
            bar_named(1, 128);
            if (t < 32)
                s_r[t] = s_g[2] * ((s_rp[0][t] + s_rp[1][t]) + (s_rp[2][t] + s_rp[3][t]));
        } else if (t < 256) {
            const int k = t - 128;
            if (k < MB) {
                s_aw[k] = px[PX_WP + k] + redS(&g_wpp[k], PSTR);
            } else if (k == MB) {
                s_g[1] = px[PX_WG] + red16_cg(g_wgp);
            }
            bar_named(2, 128);
            if (k < 32) {
                float m = -INFINITY;
                for (int q = k; q < MB; q += 32) m = fmaxf(m, s_aw[q]);
#pragma unroll
                for (int o = 16; o; o >>= 1) m = fmaxf(m, __shfl_xor_sync(0xFFFFFFFFu, m, o));
                float ssum = 0.f;
                for (int q = k; q < MB; q += 32) { float e = __expf(s_aw[q] - m); s_aw[q] = e; ssum += e; }
#pragma unroll
                for (int o = 16; o; o >>= 1) ssum += __shfl_xor_sync(0xFFFFFFFFu, ssum, o);
                if (k == 0) { s_g[3] = 1.f / (1.f + __expf(-s_g[1])); s_g[4] = 1.f / ssum; }
            }
        } else if (t < 288) {
            // c slice from DSMEM-scattered pc: 16 conflict-free LDS
            const int cl = t - 256;
            float a = px[cl];
#pragma unroll
            for (int jj = 0; jj < NC; jj++) a += s_bufpc[jj][cl];
            s_c[cl] = fmaxf(a, 0.f);
        }
        __syncthreads();                                  // S5

        // ===== pout partial: DSMEM scatter into consumer (t>>5)'s window =====
        {
            float po = acc_h;
            float po2 = 0.f;
#pragma unroll
            for (int i = 0; i < 16; i++) {
                po  = fmaf(s_r[2 * i],     wrh[2 * i],     po);
                po2 = fmaf(s_r[2 * i + 1], wrh[2 * i + 1], po2);
            }
            st_remote_f32(smem_u32(&s_bufpout[j][t & 31]), (uint32_t)(t >> 5), po + po2);
        }
        __syncthreads();                                  // S6
        if (t < NC) arrive_remote(mbarB, (uint32_t)t);

        // memory write (local; overlaps exchange-B latency)
        {
            const float gw = s_g[3], invw = s_g[4];
#pragma unroll
            for (int it = 0; it < 7; it++) {
                int idx = t + it * 512;
                if (idx < MB * 32) {
                    const int m2 = idx >> 5, cl = idx & 31;
                    const float aw = s_aw[m2] * invw;
                    s_mem[m2][cl] = gw * aw * s_c[cl] + (1.f - aw) * s_mem[m2][cl];
                }
            }
        }

        // ----- exchange B wait -----
        wait_parity_cluster(mbarB, parity);
        __syncthreads();                                  // S7

        // ===== phase 3: reduce pout window from LOCAL SMEM =====
        if (t < 32) {
            float hn = px[PX_H + t];
#pragma unroll
            for (int jj = 0; jj < NC; jj++) hn += s_bufpout[jj][t];
            hn = fmaxf(hn, 0.f);
            out[(size_t)s * H + base + t] = hn;
            s_hl[t] = hn;
        }
        __syncthreads();                                  // S8
    }
}

// ---------------- launcher ----------------
extern "C" void kernel_launch(void* const* d_in, const int* in_sizes, int n_in,
                              void* d_out, int out_size) {
    const float* X    = (const float*)d_in[0];
    const float* Wc   = (const float*)d_in[1];
    const float* bc   = (const float*)d_in[2];
    const float* Wwg  = (const float*)d_in[3];
    const float* bwg  = (const float*)d_in[4];
    const float* Wwp  = (const float*)d_in[5];
    const float* bwp  = (const float*)d_in[6];
    const float* Wrg  = (const float*)d_in[7];
    const float* brg  = (const float*)d_in[8];
    const float* Wrp  = (const float*)d_in[9];
    const float* brp  = (const float*)d_in[10];
    const float* Wxh  = (const float*)d_in[11];
    const float* Wrh  = (const float*)d_in[12];
    const float* Whh  = (const float*)d_in[13];
    const float* bh   = (const float*)d_in[14];
    const int*   nImg = (const int*)d_in[15];

    prep_kernel<<<(ISZ * STRIDE + 255) / 256, 256>>>(Wc, bc, Wwg, bwg, Wwp, bwp,
                                                     Wrg, brg, Wrp, brp, Wxh, bh);
    dim3 ggrid(NSTEPS_MAX / 128, STRIDE / 64);
    gemm_kernel<<<ggrid, 256>>>(X);

    // one cluster of 16 CTAs (nonportable size opt-in)
    static bool attr_done = false;
    if (!attr_done) {
        cudaFuncSetAttribute((const void*)recur_kernel,
                             cudaFuncAttributeNonPortableClusterSizeAllowed, 1);
        attr_done = true;
    }
    cudaLaunchConfig_t cfg = {};
    cfg.gridDim  = dim3(NC, 1, 1);
    cfg.blockDim = dim3(512, 1, 1);
    cfg.dynamicSmemBytes = 0;
    cudaLaunchAttribute attrs[1];
    attrs[0].id = cudaLaunchAttributeClusterDimension;
    attrs[0].val.clusterDim.x = NC;
    attrs[0].val.clusterDim.y = 1;
    attrs[0].val.clusterDim.z = 1;
    cfg.attrs = attrs;
    cfg.numAttrs = 1;
    cudaLaunchKernelEx(&cfg, recur_kernel,
                       Wc, Wrg, Wrp, Wwg, Wwp, Wrh, Whh, (float*)d_out, nImg);
}

// round 15
// speedup vs baseline: 2.1891x; 1.2384x over previous
#include <cuda_runtime.h>
#include <cuda_bf16.h>
#include <math.h>
#include <stdint.h>

// Problem constants
#define NSTEPS_MAX 32768
#define ISZ 1024
#define H   512
#define MB  100

// Px layout (per-step precomputed x-projections + biases), padded stride
#define STRIDE 1280
#define OFF_C  0      // 512: x@Wc_x + bc
#define OFF_WG 512    // 1  : x@Wwg_x + bwg
#define OFF_WP 516    // 100: x@Wwp_x + bwp
#define OFF_RG 616    // 1
#define OFF_RP 620    // 100
#define OFF_H  720    // 512: x@Wxh + bh

#define NC 16         // CTAs in recurrence kernel (one cluster)
#define PSTR 128      // padded stride for MB-sized partial blocks

// ---------------- device global scratch (no runtime alloc allowed) ----------------
__device__ float g_Px[(size_t)NSTEPS_MAX * STRIDE];   // ~168 MB
__device__ float g_Wcat[(size_t)ISZ * STRIDE];        // 5.2 MB
__device__ float g_bcat[STRIDE];

// all-to-all partials stay in L2: producer-coalesced layout [cta][elem]
__device__ __align__(16) float g_rpp[NC * PSTR];
__device__ __align__(16) float g_wpp[NC * PSTR];
__device__ __align__(16) float g_rgp[NC];
__device__ __align__(16) float g_wgp[NC];

// ---------------- PTX helpers ----------------
__device__ __forceinline__ uint32_t smem_u32(const void* p) {
    return (uint32_t)__cvta_generic_to_shared(p);
}
__device__ __forceinline__ void mbar_init(uint32_t addr, uint32_t cnt) {
    asm volatile("mbarrier.init.shared.b64 [%0], %1;" :: "r"(addr), "r"(cnt) : "memory");
}
__device__ __forceinline__ uint32_t mapa_u32(uint32_t laddr, uint32_t rank) {
    uint32_t r;
    asm volatile("mapa.shared::cluster.u32 %0, %1, %2;" : "=r"(r) : "r"(laddr), "r"(rank));
    return r;
}
// remote store of one float into peer CTA's SMEM (plain)
__device__ __forceinline__ void st_remote_f32(uint32_t laddr, uint32_t rank, float v) {
    uint32_t r = mapa_u32(laddr, rank);
    asm volatile("st.shared::cluster.f32 [%0], %1;" :: "r"(r), "f"(v) : "memory");
}
// async remote store that credits 4 bytes to the TARGET CTA's mbarrier
__device__ __forceinline__ void st_async_f32(uint32_t laddr, uint32_t lmbar, uint32_t rank, float v) {
    uint32_t ra = mapa_u32(laddr, rank);
    uint32_t rb = mapa_u32(lmbar, rank);
    asm volatile("st.async.shared::cluster.mbarrier::complete_tx::bytes.f32 [%0], %1, [%2];"
                 :: "r"(ra), "f"(v), "r"(rb) : "memory");
}
__device__ __forceinline__ void mbar_arrive_expect_tx(uint32_t addr, uint32_t bytes) {
    asm volatile("mbarrier.arrive.expect_tx.shared.b64 _, [%0], %1;"
                 :: "r"(addr), "r"(bytes) : "memory");
}
// remote mbarrier arrive with cluster-scope release (cumulative)
__device__ __forceinline__ void arrive_remote(uint32_t laddr, uint32_t rank) {
    uint32_t r = mapa_u32(laddr, rank);
    asm volatile("mbarrier.arrive.release.cluster.shared::cluster.b64 _, [%0];" :: "r"(r) : "memory");
}
// parity wait with cluster-scope acquire
__device__ __forceinline__ void wait_parity_cluster(uint32_t addr, uint32_t parity) {
    uint32_t done;
    asm volatile(
        "{\n\t.reg .pred p;\n\t"
        "mbarrier.try_wait.parity.acquire.cluster.shared::cta.b64 p, [%1], %2;\n\t"
        "selp.b32 %0, 1, 0, p;\n\t}"
        : "=r"(done) : "r"(addr), "r"(parity) : "memory");
    if (!done) {
        asm volatile(
            "{\n\t.reg .pred P1;\n\t"
            "WAIT_LOOP_%=:\n\t"
            "mbarrier.try_wait.parity.acquire.cluster.shared::cta.b64 P1, [%0], %1, 0x989680;\n\t"
            "@P1 bra.uni WAIT_DONE_%=;\n\t"
            "bra.uni WAIT_LOOP_%=;\n\t"
            "WAIT_DONE_%=:\n\t}"
            :: "r"(addr), "r"(parity) : "memory");
    }
}
__device__ __forceinline__ void cluster_sync_all() {
    asm volatile("barrier.cluster.arrive.aligned;" ::: "memory");
    asm volatile("barrier.cluster.wait.aligned;" ::: "memory");
}
__device__ __forceinline__ void bar_named(int id, int cnt) {
    asm volatile("bar.sync %0, %1;" :: "r"(id), "r"(cnt) : "memory");
}

// ---------------- kernel 1: build concatenated weight/bias ----------------
__global__ void prep_kernel(const float* __restrict__ Wc,  const float* __restrict__ bc,
                            const float* __restrict__ Wwg, const float* __restrict__ bwg,
                            const float* __restrict__ Wwp, const float* __restrict__ bwp,
                            const float* __restrict__ Wrg, const float* __restrict__ brg,
                            const float* __restrict__ Wrp, const float* __restrict__ brp,
                            const float* __restrict__ Wxh, const float* __restrict__ bh) {
    int idx = blockIdx.x * blockDim.x + threadIdx.x;
    if (idx < ISZ * STRIDE) {
        int k = idx / STRIDE, n = idx % STRIDE;
        float v = 0.f;
        if (n < 512)                          v = Wc[(size_t)k * H + n];
        else if (n == OFF_WG)                 v = Wwg[k];
        else if (n >= OFF_WP && n < OFF_WP + MB) v = Wwp[(size_t)k * MB + (n - OFF_WP)];
        else if (n == OFF_RG)                 v = Wrg[k];
        else if (n >= OFF_RP && n < OFF_RP + MB) v = Wrp[(size_t)k * MB + (n - OFF_RP)];
        else if (n >= OFF_H && n < OFF_H + H) v = Wxh[(size_t)k * H + (n - OFF_H)];
        g_Wcat[idx] = v;
    }
    if (idx < STRIDE) {
        int n = idx;
        float b = 0.f;
        if (n < 512)                          b = bc[n];
        else if (n == OFF_WG)                 b = bwg[0];
        else if (n >= OFF_WP && n < OFF_WP + MB) b = bwp[n - OFF_WP];
        else if (n == OFF_RG)                 b = brg[0];
        else if (n >= OFF_RP && n < OFF_RP + MB) b = brp[n - OFF_RP];
        else if (n >= OFF_H && n < OFF_H + H) b = bh[n - OFF_H];
        g_bcat[n] = b;
    }
}

// ---------------- kernel 2: Px = X @ Wcat + bcat (tiled fp32 GEMM) ----------------
__global__ void __launch_bounds__(256) gemm_kernel(const float* __restrict__ X) {
    __shared__ float As[16][128];
    __shared__ float Bs[16][64];

    const int tid = threadIdx.x;
    const int bm = blockIdx.x * 128;
    const int bn = blockIdx.y * 64;

    const int ty = tid >> 4;
    const int tx = tid & 15;

    float acc[8][4];
#pragma unroll
    for (int i = 0; i < 8; i++)
#pragma unroll
        for (int j = 0; j < 4; j++) acc[i][j] = 0.f;

    const int a_m = tid >> 2;
    const int a_k = (tid & 3) * 4;
    const int b_k = tid >> 4;
    const int b_n = (tid & 15) * 4;

    for (int k0 = 0; k0 < ISZ; k0 += 16) {
        float4 v0 = *reinterpret_cast<const float4*>(&X[(size_t)(bm + a_m) * ISZ + k0 + a_k]);
        float4 v1 = *reinterpret_cast<const float4*>(&X[(size_t)(bm + a_m + 64) * ISZ + k0 + a_k]);
        float4 w  = *reinterpret_cast<const float4*>(&g_Wcat[(size_t)(k0 + b_k) * STRIDE + bn + b_n]);
        As[a_k + 0][a_m] = v0.x; As[a_k + 1][a_m] = v0.y;
        As[a_k + 2][a_m] = v0.z; As[a_k + 3][a_m] = v0.w;
        As[a_k + 0][a_m + 64] = v1.x; As[a_k + 1][a_m + 64] = v1.y;
        As[a_k + 2][a_m + 64] = v1.z; As[a_k + 3][a_m + 64] = v1.w;
        *reinterpret_cast<float4*>(&Bs[b_k][b_n]) = w;
        __syncthreads();
#pragma unroll
        for (int kk = 0; kk < 16; kk++) {
            float a[8], b[4];
#pragma unroll
            for (int i = 0; i < 8; i++) a[i] = As[kk][ty * 8 + i];
#pragma unroll
            for (int j = 0; j < 4; j++) b[j] = Bs[kk][tx * 4 + j];
#pragma unroll
            for (int i = 0; i < 8; i++)
#pragma unroll
                for (int j = 0; j < 4; j++) acc[i][j] = fmaf(a[i], b[j], acc[i][j]);
        }
        __syncthreads();
    }
#pragma unroll
    for (int i = 0; i < 8; i++) {
        int row = bm + ty * 8 + i;
        int col = bn + tx * 4;
        float4 o;
        o.x = acc[i][0] + g_bcat[col + 0];
        o.y = acc[i][1] + g_bcat[col + 1];
        o.z = acc[i][2] + g_bcat[col + 2];
        o.w = acc[i][3] + g_bcat[col + 3];
        *reinterpret_cast<float4*>(&g_Px[(size_t)row * STRIDE + col]) = o;
    }
}

// ---------------- reduction helpers ----------------
__device__ __forceinline__ float redS(const float* p, int stride) {
    float v[16];
#pragma unroll
    for (int k = 0; k < 16; k++) v[k] = __ldcg(p + k * stride);
    float s0 = (v[0] + v[1]) + (v[2] + v[3]);
    float s1 = (v[4] + v[5]) + (v[6] + v[7]);
    float s2 = (v[8] + v[9]) + (v[10] + v[11]);
    float s3 = (v[12] + v[13]) + (v[14] + v[15]);
    return (s0 + s1) + (s2 + s3);
}
__device__ __forceinline__ float red16_cg(const float* p) {
    float4 a = __ldcg((const float4*)(p + 0));
    float4 b = __ldcg((const float4*)(p + 4));
    float4 c = __ldcg((const float4*)(p + 8));
    float4 d = __ldcg((const float4*)(p + 12));
    return ((a.x + a.y) + (a.z + a.w)) + ((b.x + b.y) + (b.z + b.w))
         + ((c.x + c.y) + (c.z + c.w)) + ((d.x + d.y) + (d.z + d.w));
}

// SMEM px tile layout (272 floats)
#define PX_WG 32
#define PX_WP 36
#define PX_RG 136
#define PX_RP 140
#define PX_H  240

#define POUT_TX_BYTES (NC * 32 * 4)   // 2048: bytes expected at mbarB per step

// ---------------- kernel 3: sequential recurrence (cluster of 16 CTAs x 512) ----------------
__global__ void __launch_bounds__(512, 1) recur_kernel(
    const float* __restrict__ Wc,  const float* __restrict__ Wrg,
    const float* __restrict__ Wrp, const float* __restrict__ Wwg,
    const float* __restrict__ Wwp, const float* __restrict__ Wrh,
    const float* __restrict__ Whh, float* __restrict__ out,
    const int* __restrict__ nImgP) {

    __shared__ float s_hl[32];
    __shared__ float s_wrp[MB][33];
    __shared__ float s_wwp[MB][33];
    __shared__ float s_wrg[32];
    __shared__ float s_wwg[32];
    __shared__ float s_mem[MB][33];
    __shared__ float s_ar[MB];              // exp(e_r), unnormalized
    __shared__ float s_aw[MB];              // exp(e_w), unnormalized
    __shared__ float s_c[32];
    __shared__ float s_r[32];
    __shared__ float s_rp[4][33];
    __shared__ float s_g[8];   // 0=rg logit 1=wg logit 2=go/sum_r 3=gw 4=inv_sum_w
    __shared__ __align__(16) float s_px[2][272];
    __shared__ float s_bufpc[NC][32];       // DSMEM-scattered pc window
    __shared__ float s_bufpout[NC][32];     // DSMEM-scattered pout window (tx-tracked)
    __shared__ __align__(8) unsigned long long s_mbar[2];  // [0]=A (count 16), [1]=B (count 1 + tx)

    const int t = threadIdx.x;
    const int j = blockIdx.x;
    const int base = j * 32;

    const uint32_t mbarA = smem_u32(&s_mbar[0]);
    const uint32_t mbarB = smem_u32(&s_mbar[1]);

    // register-resident weight columns: thread t owns output column t
    float wc[32], whh[32], wrh[32];
#pragma unroll
    for (int i = 0; i < 32; i++) {
        wc[i]  = Wc[(size_t)(ISZ + base + i) * H + t];
        whh[i] = Whh[(size_t)(base + i) * H + t];
        wrh[i] = Wrh[(size_t)(base + i) * H + t];
    }
    for (int idx = t; idx < MB * 32; idx += 512) {
        int k = idx >> 5, i = idx & 31;
        s_wrp[k][i] = Wrp[(size_t)(ISZ + base + i) * MB + k];
        s_wwp[k][i] = Wwp[(size_t)(ISZ + base + i) * MB + k];
    }
    if (t < 32) { s_wrg[t] = Wrg[ISZ + base + t]; s_wwg[t] = Wwg[ISZ + base + t]; }
    for (int idx = t; idx < MB * 33; idx += 512) ((float*)s_mem)[idx] = 0.f;
    if (t < 32) s_hl[t] = 0.f;
    if (t == 0) { mbar_init(mbarA, NC); mbar_init(mbarB, 1); }
    __syncthreads();
    cluster_sync_all();   // all mbarriers initialized before any remote op

    int nSteps = *nImgP;
    if (nSteps > NSTEPS_MAX) nSteps = NSTEPS_MAX;
    if (nSteps <= 0) nSteps = 1;

    // --- prologue prefetch: step 0 into buffer 0 ---
    {
        const float* row = g_Px;
        if (t < 68) {
            const float* src; float* dst;
            if (t < 8)       { src = row + OFF_C + base + t * 4;        dst = &s_px[0][t * 4]; }
            else if (t < 60) { src = row + 512 + (t - 8) * 4;           dst = &s_px[0][32 + (t - 8) * 4]; }
            else             { src = row + OFF_H + base + (t - 60) * 4; dst = &s_px[0][240 + (t - 60) * 4]; }
            unsigned ds = (unsigned)__cvta_generic_to_shared(dst);
            asm volatile("cp.async.cg.shared.global [%0], [%1], 16;" :: "r"(ds), "l"(src));
        }
        asm volatile("cp.async.commit_group;" ::: "memory");
    }

    for (int s = 0; s < nSteps; s++) {
        const int cur = s & 1;
        const uint32_t parity = (uint32_t)(s & 1);

        // arm exchange B for this step BEFORE arriving at A (ordering guarantee:
        // producers' st.async are gated by exchange A, which we join only below)
        if (t == 0) mbar_arrive_expect_tx(mbarB, POUT_TX_BYTES);

        // --- prefetch step s+1 into other buffer ---
        {
            int sp = s + 1; if (sp >= nSteps) sp = nSteps - 1;
            const float* row = g_Px + (size_t)sp * STRIDE;
            if (t < 68) {
                const float* src; float* dst;
                if (t < 8)       { src = row + OFF_C + base + t * 4;        dst = &s_px[cur ^ 1][t * 4]; }
                else if (t < 60) { src = row + 512 + (t - 8) * 4;           dst = &s_px[cur ^ 1][32 + (t - 8) * 4]; }
                else             { src = row + OFF_H + base + (t - 60) * 4; dst = &s_px[cur ^ 1][240 + (t - 60) * 4]; }
                unsigned ds = (unsigned)__cvta_generic_to_shared(dst);
                asm volatile("cp.async.cg.shared.global [%0], [%1], 16;" :: "r"(ds), "l"(src));
            }
            asm volatile("cp.async.commit_group;" ::: "memory");
        }

        // ===== phase 1: h-slice projections =====
        {
            float acc = 0.f;
#pragma unroll
            for (int i = 0; i < 32; i++) acc = fmaf(s_hl[i], wc[i], acc);
            st_remote_f32(smem_u32(&s_bufpc[j][t & 31]), (uint32_t)(t >> 5), acc);
        }
        if (t < MB) {
            float a = 0.f;
#pragma unroll
            for (int i = 0; i < 32; i++) a = fmaf(s_wrp[t][i], s_hl[i], a);
            __stcg(&g_rpp[j * PSTR + t], a);
        } else if (t < 2 * MB) {
            const int k = t - MB;
            float a = 0.f;
#pragma unroll
            for (int i = 0; i < 32; i++) a = fmaf(s_wwp[k][i], s_hl[i], a);
            __stcg(&g_wpp[j * PSTR + k], a);
        } else if (t == 200) {
            float a = 0.f;
#pragma unroll
            for (int i = 0; i < 32; i++) a = fmaf(s_wrg[i], s_hl[i], a);
            __stcg(&g_rgp[j], a);
        } else if (t == 201) {
            float a = 0.f;
#pragma unroll
            for (int i = 0; i < 32; i++) a = fmaf(s_wwg[i], s_hl[i], a);
            __stcg(&g_wgp[j], a);
        }

        __syncthreads();                                  // S1: all stores issued
        if (t < NC) arrive_remote(mbarA, (uint32_t)t);    // release.cluster (cumulative)

        // in the waitA shadow: h-part of pout + prefetch drain
        float acc_h = 0.f;
#pragma unroll
        for (int i = 0; i < 32; i++) acc_h = fmaf(s_hl[i], whh[i], acc_h);
        asm volatile("cp.async.wait_group 1;" ::: "memory");

        // ----- exchange A wait -----
        wait_parity_cluster(mbarA, parity);
        __syncthreads();                                  // S2

        const float* px = s_px[cur];

        // ===== attention paths in barrier groups (no max-pass softmax) =====
        if (t < 128) {
            if (t < MB) {
                float e = px[PX_RP + t] + redS(&g_rpp[t], PSTR);
                s_ar[t] = __expf(e);                      // unnormalized
            } else if (t == MB) {
                s_g[0] = px[PX_RG] + red16_cg(g_rgp);
            }
            bar_named(1, 128);
            // warp 0: sum of exps + gate fold (while warps 1-3 start ar@mem)
            if (t < 32) {
                float ssum = 0.f;
                for (int k = t; k < MB; k += 32) ssum += s_ar[k];
#pragma unroll
                for (int o = 16; o; o >>= 1) ssum += __shfl_xor_sync(0xFFFFFFFFu, ssum, o);
                if (t == 0) s_g[2] = (1.f / (1.f + __expf(-s_g[0]))) / ssum;   // go / sum_r
            }
            // warps 0-3: 4-way split of ar @ mem
            {
                const int part = t >> 5, col = t & 31;
                const int m0 = part * 25;
                float a = 0.f;
#pragma unroll
                for (int m2 = 0; m2 < 25; m2++) a = fmaf(s_ar[m0 + m2], s_mem[m0 + m2][col], a);
                s_rp[part][col] = a;
            }
            bar_named(1, 128);
            if (t < 32)
                s_r[t] = s_g[2] * ((s_rp[0][t] + s_rp[1][t]) + (s_rp[2][t] + s_rp[3][t]));
        } else if (t < 256) {
            const int k = t - 128;
            if (k < MB) {
                float e = px[PX_WP + k] + redS(&g_wpp[k], PSTR);
                s_aw[k] = __expf(e);                      // unnormalized
            } else if (k == MB) {
                s_g[1] = px[PX_WG] + red16_cg(g_wgp);
            }
            bar_named(2, 128);
            if (k < 32) {
                float ssum = 0.f;
                for (int q = k; q < MB; q += 32) ssum += s_aw[q];
#pragma unroll
                for (int o = 16; o; o >>= 1) ssum += __shfl_xor_sync(0xFFFFFFFFu, ssum, o);
                if (k == 0) { s_g[3] = 1.f / (1.f + __expf(-s_g[1])); s_g[4] = 1.f / ssum; }
            }
        } else if (t < 288) {
            // c slice from DSMEM-scattered pc
            const int cl = t - 256;
            float a = px[cl];
#pragma unroll
            for (int jj = 0; jj < NC; jj++) a += s_bufpc[jj][cl];
            s_c[cl] = fmaxf(a, 0.f);
        }
        __syncthreads();                                  // S5

        // ===== pout partial: tx-tracked async scatter (data IS the signal) =====
        {
            float po = acc_h;
            float po2 = 0.f;
#pragma unroll
            for (int i = 0; i < 16; i++) {
                po  = fmaf(s_r[2 * i],     wrh[2 * i],     po);
                po2 = fmaf(s_r[2 * i + 1], wrh[2 * i + 1], po2);
            }
            st_async_f32(smem_u32(&s_bufpout[j][t & 31]), mbarB, (uint32_t)(t >> 5), po + po2);
        }

        // memory write (local; overlaps exchange-B delivery)
        {
            const float gw = s_g[3], invw = s_g[4];
#pragma unroll
            for (int it = 0; it < 7; it++) {
                int idx = t + it * 512;
                if (idx < MB * 32) {
                    const int m2 = idx >> 5, cl = idx & 31;
                    const float aw = s_aw[m2] * invw;
                    s_mem[m2][cl] = gw * aw * s_c[cl] + (1.f - aw) * s_mem[m2][cl];
                }
            }
        }

        // ----- exchange B wait (completes when all 2048 bytes landed) -----
        wait_parity_cluster(mbarB, parity);
        __syncthreads();                                  // S7

        // ===== phase 3: reduce pout window from LOCAL SMEM =====
        if (t < 32) {
            float hn = px[PX_H + t];
#pragma unroll
            for (int jj = 0; jj < NC; jj++) hn += s_bufpout[jj][t];
            hn = fmaxf(hn, 0.f);
            out[(size_t)s * H + base + t] = hn;
            s_hl[t] = hn;
        }
        __syncthreads();                                  // S8
    }
}

// ---------------- launcher ----------------
extern "C" void kernel_launch(void* const* d_in, const int* in_sizes, int n_in,
                              void* d_out, int out_size) {
    const float* X    = (const float*)d_in[0];
    const float* Wc   = (const float*)d_in[1];
    const float* bc   = (const float*)d_in[2];
    const float* Wwg  = (const float*)d_in[3];
    const float* bwg  = (const float*)d_in[4];
    const float* Wwp  = (const float*)d_in[5];
    const float* bwp  = (const float*)d_in[6];
    const float* Wrg  = (const float*)d_in[7];
    const float* brg  = (const float*)d_in[8];
    const float* Wrp  = (const float*)d_in[9];
    const float* brp  = (const float*)d_in[10];
    const float* Wxh  = (const float*)d_in[11];
    const float* Wrh  = (const float*)d_in[12];
    const float* Whh  = (const float*)d_in[13];
    const float* bh   = (const float*)d_in[14];
    const int*   nImg = (const int*)d_in[15];

    prep_kernel<<<(ISZ * STRIDE + 255) / 256, 256>>>(Wc, bc, Wwg, bwg, Wwp, bwp,
                                                     Wrg, brg, Wrp, brp, Wxh, bh);
    dim3 ggrid(NSTEPS_MAX / 128, STRIDE / 64);
    gemm_kernel<<<ggrid, 256>>>(X);

    // one cluster of 16 CTAs (nonportable size opt-in)
    static bool attr_done = false;
    if (!attr_done) {
        cudaFuncSetAttribute((const void*)recur_kernel,
                             cudaFuncAttributeNonPortableClusterSizeAllowed, 1);
        attr_done = true;
    }
    cudaLaunchConfig_t cfg = {};
    cfg.gridDim  = dim3(NC, 1, 1);
    cfg.blockDim = dim3(512, 1, 1);
    cfg.dynamicSmemBytes = 0;
    cudaLaunchAttribute attrs[1];
    attrs[0].id = cudaLaunchAttributeClusterDimension;
    attrs[0].val.clusterDim.x = NC;
    attrs[0].val.clusterDim.y = 1;
    attrs[0].val.clusterDim.z = 1;
    cfg.attrs = attrs;
    cfg.numAttrs = 1;
    cudaLaunchKernelEx(&cfg, recur_kernel,
                       Wc, Wrg, Wrp, Wwg, Wwp, Wrh, Whh, (float*)d_out, nImg);
}